// round 13
// baseline (speedup 1.0000x reference)
#include <cuda_runtime.h>
#include <cuda_bf16.h>
#include <cstdint>
#include <cstddef>

#define B_TOT 32768
#define D_IN  128
#define A_DIM 16
#define H1D   600
#define H2D   500
#define KP    640
#define G_N   8

// ---- shared A-staging geometry (both GEMMs): 128 rows x 144B per half ----
#define ROWB   144u
#define AHALF  18432u
#define ASTAGE (2u*AHALF)            // 36864
#define GEMM_SMEM (2*ASTAGE + 1024)  // 2 stages + bias/idx tail

// ---- persistent device scratch ----
__device__ __nv_bfloat16 g_h1hi[(size_t)B_TOT * KP];
__device__ __nv_bfloat16 g_h1lo[(size_t)B_TOT * KP];
__device__ __nv_bfloat16 g_Sh[(size_t)B_TOT * D_IN];
__device__ __nv_bfloat16 g_Sl[(size_t)B_TOT * D_IN];
// B fragments, layout: [unit][lane][h] -> uint64 pair per lane = one uint4 (hi,lo)
__device__ uint64_t g_W1f[(size_t)G_N * 8 * 80 * 32 * 2];  // [g][kq<8][n8<80]
__device__ uint64_t g_W2f[(size_t)36 * 64 * 32 * 2];       // [kq<36][n8<64]
__device__ uint64_t g_Btf[(size_t)G_N * 4 * 64 * 32 * 2];  // [g][kk<4][n8<64] tail k 576..639

// ---------------- helpers ----------------
__device__ __forceinline__ uint32_t smem_u32(const void* p) {
    uint32_t a;
    asm("{ .reg .u64 t; cvta.to.shared.u64 t, %1; cvt.u32.u64 %0, t; }" : "=r"(a) : "l"(p));
    return a;
}
__device__ __forceinline__ void ldm_x4(uint32_t* r, uint32_t addr) {
    asm volatile("ldmatrix.sync.aligned.m8n8.x4.shared.b16 {%0,%1,%2,%3}, [%4];"
                 : "=r"(r[0]), "=r"(r[1]), "=r"(r[2]), "=r"(r[3]) : "r"(addr));
}
__device__ __forceinline__ void mma16816(float* c, const uint32_t* a, const uint32_t* b) {
    asm volatile("mma.sync.aligned.m16n8k16.row.col.f32.bf16.bf16.f32 "
                 "{%0,%1,%2,%3}, {%4,%5,%6,%7}, {%8,%9}, {%0,%1,%2,%3};"
                 : "+f"(c[0]), "+f"(c[1]), "+f"(c[2]), "+f"(c[3])
                 : "r"(a[0]), "r"(a[1]), "r"(a[2]), "r"(a[3]), "r"(b[0]), "r"(b[1]));
}
__device__ __forceinline__ void cp16(uint32_t dst, const void* src) {
    asm volatile("cp.async.cg.shared.global [%0], [%1], 16;" :: "r"(dst), "l"(src) : "memory");
}
__device__ __forceinline__ void cp_commit() { asm volatile("cp.async.commit_group;" ::: "memory"); }
__device__ __forceinline__ void cp_wait0() { asm volatile("cp.async.wait_group 0;" ::: "memory"); }

__device__ __forceinline__ uint32_t pack2(float f0, float f1) {
    uint32_t r;
    asm("cvt.rn.bf16x2.f32 %0, %1, %2;" : "=r"(r) : "f"(f1), "f"(f0));
    return r;
}
__device__ __forceinline__ void split2(float f0, float f1, uint32_t& h, uint32_t& l) {
    h = pack2(f0, f1);
    float h0 = __uint_as_float(h << 16);
    float h1 = __uint_as_float(h & 0xffff0000u);
    l = pack2(f0 - h0, f1 - h1);
}
__device__ __forceinline__ void split8(float4 v0, float4 v1, uint4& H, uint4& L) {
    split2(v0.x, v0.y, H.x, L.x);
    split2(v0.z, v0.w, H.y, L.y);
    split2(v1.x, v1.y, H.z, L.z);
    split2(v1.z, v1.w, H.w, L.w);
}

// ---------------- fused prep kernel ----------------
// [0,128) init_out | [128,256) fill_pad | [256,2304) split_state
// [2304,2944) W1 frags | [2944,3232) W2 frags | [3232,3488) Btail frags
#define PREP_BLOCKS 3488
__global__ __launch_bounds__(256) void prep_kernel(const float* __restrict__ state,
                                                   const float* __restrict__ action,
                                                   const int* __restrict__ idx,
                                                   const float* __restrict__ W1,
                                                   const float* __restrict__ W2s,
                                                   const float* __restrict__ W2a,
                                                   const float* __restrict__ b3,
                                                   float* __restrict__ out) {
    const int blk = blockIdx.x;
    const int t = threadIdx.x;
    if (blk < 128) {
        int i = blk * 256 + t;
        out[i] = b3[idx[i]];
    } else if (blk < 256) {
        int b = (blk - 128) * 256 + t;
        const float4* a4 = (const float4*)(action + (size_t)b * A_DIM);
        uint4 H0, L0, H1, L1;
        split8(a4[0], a4[1], H0, L0);
        split8(a4[2], a4[3], H1, L1);
        uint16_t* ph = (uint16_t*)g_h1hi + (size_t)b * KP + 600;
        uint16_t* pl = (uint16_t*)g_h1lo + (size_t)b * KP + 600;
        ((uint4*)ph)[0] = H0; ((uint4*)ph)[1] = H1;
        ((uint4*)pl)[0] = L0; ((uint4*)pl)[1] = L1;
        uint4 z = make_uint4(0, 0, 0, 0);
        ((uint4*)(ph + 16))[0] = z; ((uint4*)(ph + 16))[1] = z; ((uint4*)(ph + 16))[2] = z;
        ((uint4*)(pl + 16))[0] = z; ((uint4*)(pl + 16))[1] = z; ((uint4*)(pl + 16))[2] = z;
    } else if (blk < 2304) {
        size_t e = ((size_t)(blk - 256) * 256 + t) * 8;
        const float4* s4 = (const float4*)(state + e);
        uint4 H, L;
        split8(s4[0], s4[1], H, L);
        *(uint4*)((uint16_t*)g_Sh + e) = H;
        *(uint4*)((uint16_t*)g_Sl + e) = L;
    } else if (blk < 2944) {
        // W1 fragment units: u in [0, 163840); lane | n8<80 | gkq<64
        int u = (blk - 2304) * 256 + t;
        int lane = u & 31;
        int r5 = u >> 5;
        int n8 = r5 % 80;
        int gkq = r5 / 80;
        int g = gkq >> 3, kq = gkq & 7;
        int n = n8 * 8 + (lane >> 2);
        int k0 = kq * 16 + (lane & 3) * 2;
        float x0 = 0.f, x1 = 0.f, x2 = 0.f, x3 = 0.f;
        if (n < H1D) {
            const float* w = W1 + ((size_t)g * H1D + n) * D_IN;
            x0 = w[k0]; x1 = w[k0 + 1]; x2 = w[k0 + 8]; x3 = w[k0 + 9];
        }
        uint32_t h0, l0, h1, l1;
        split2(x0, x1, h0, l0);
        split2(x2, x3, h1, l1);
        size_t base = ((size_t)(gkq * 80 + n8) * 32 + lane) * 2;
        g_W1f[base]     = (uint64_t)h0 | ((uint64_t)h1 << 32);
        g_W1f[base + 1] = (uint64_t)l0 | ((uint64_t)l1 << 32);
    } else if (blk < 3232) {
        // W2 fragment units: kq in [0,36)
        int u = (blk - 2944) * 256 + t;     // [0, 73728)
        int lane = u & 31;
        int n8 = (u >> 5) & 63;
        int kq = u >> 11;
        int n = n8 * 8 + (lane >> 2);
        int k0 = kq * 16 + (lane & 3) * 2;
        float x0 = 0.f, x1 = 0.f, x2 = 0.f, x3 = 0.f;
        if (n < H2D) {
            const float* w = W2s + (size_t)n * H1D;
            x0 = w[k0]; x1 = w[k0 + 1]; x2 = w[k0 + 8]; x3 = w[k0 + 9];
        }
        uint32_t h0, l0, h1, l1;
        split2(x0, x1, h0, l0);
        split2(x2, x3, h1, l1);
        size_t base = ((size_t)(kq * 64 + n8) * 32 + lane) * 2;
        g_W2f[base]     = (uint64_t)h0 | ((uint64_t)h1 << 32);
        g_W2f[base + 1] = (uint64_t)l0 | ((uint64_t)l1 << 32);
    } else {
        // B tail fragment units: gk = g*4+kk in [0,32)
        int u = (blk - 3232) * 256 + t;     // [0, 65536)
        int lane = u & 31;
        int n8 = (u >> 5) & 63;
        int gk = u >> 11;
        int g = gk >> 2, kk = gk & 3;
        int n = n8 * 8 + (lane >> 2);
        int c0 = kk * 16 + (lane & 3) * 2;
        float v[4];
        const int off[4] = {0, 1, 8, 9};
        #pragma unroll
        for (int j = 0; j < 4; j++) {
            int tc = 576 + c0 + off[j];
            float x = 0.f;
            if (n < H2D) {
                if (tc < H1D) x = W2s[(size_t)n * H1D + tc];
                else if (tc < H1D + A_DIM) x = W2a[((size_t)g * H2D + n) * A_DIM + (tc - H1D)];
            }
            v[j] = x;
        }
        uint32_t h0, l0, h1, l1;
        split2(v[0], v[1], h0, l0);
        split2(v[2], v[3], h1, l1);
        size_t base = ((size_t)(gk * 64 + n8) * 32 + lane) * 2;
        g_Btf[base]     = (uint64_t)h0 | ((uint64_t)h1 << 32);
        g_Btf[base + 1] = (uint64_t)l0 | ((uint64_t)l1 << 32);
    }
}

// ========== GEMM1: M=128,N=64,K=128; A resident in smem, B via fragment LDG.128 ==========
__global__ __launch_bounds__(256, 2) void h1_mma_kernel(const int* __restrict__ idx,
                                                        const float* __restrict__ b1) {
    extern __shared__ char dsm[];
    const uint32_t sbase = smem_u32(dsm);
    float* sb1 = (float*)(dsm + 2 * ASTAGE);
    int* sidx = (int*)(sb1 + 64);
    const int tid = threadIdx.x, lane = tid & 31, wid = tid >> 5;
    const int n0 = blockIdx.x * 64, b0 = blockIdx.y * 128;
    if (tid < 128) sidx[tid] = idx[b0 + tid];
    const int m_base = (wid >> 1) * 32, n_base = (wid & 1) * 32;
    const uint32_t aoff = (uint32_t)(m_base + (lane & 15)) * ROWB + (uint32_t)((lane >> 4) * 16);
    const int ngbase = (n0 >> 3) + (n_base >> 3);   // [0,80)

    // Load A (state) once: both K-chunks into the two resident stages
    #pragma unroll
    for (int s = 0; s < 2; s++) {
        #pragma unroll
        for (int i = 0; i < 8; i++) {
            int bid = tid + i * 256;
            int arr = bid >> 10, rem = bid & 1023;
            int row = rem >> 3, q = rem & 7;
            const __nv_bfloat16* src = (arr ? g_Sl : g_Sh) + (size_t)(b0 + row) * D_IN + s * 64 + q * 8;
            cp16(sbase + (uint32_t)s * ASTAGE + (uint32_t)arr * AHALF + row * ROWB + q * 16u, src);
        }
    }
    cp_commit();
    cp_wait0();
    __syncthreads();
    const int g_lo = sidx[0], g_hi = sidx[127];

    auto loadB = [&](uint4 (&bb)[4], int g, int kq) {
        size_t base = (size_t)((g * 8 + kq) * 80 + ngbase) * 32 + lane;
        const uint4* src = (const uint4*)g_W1f;
        #pragma unroll
        for (int nf = 0; nf < 4; nf++)
            bb[nf] = __ldg(src + base + (size_t)nf * 32);
    };

    for (int g = g_lo; g <= g_hi; ++g) {
        if (tid < 64) { int n = n0 + tid; sb1[tid] = (n < H1D) ? b1[(size_t)g * H1D + n] : 0.f; }
        __syncthreads();

        float C[2][4][4];
        #pragma unroll
        for (int mf = 0; mf < 2; mf++)
            #pragma unroll
            for (int nf = 0; nf < 4; nf++)
                #pragma unroll
                for (int e = 0; e < 4; e++) C[mf][nf][e] = 0.f;

        uint4 bb[2][4];
        loadB(bb[0], g, 0);
        #pragma unroll
        for (int kq = 0; kq < 8; ++kq) {
            const int p = kq & 1;
            if (kq < 7) loadB(bb[p ^ 1], g, kq + 1);
            const uint32_t SA = sbase + (uint32_t)(kq >> 2) * ASTAGE;
            const uint32_t SAh = SA, SAl = SA + AHALF;
            const int kk = kq & 3;
            uint32_t ah[2][4], al[2][4];
            #pragma unroll
            for (int mf = 0; mf < 2; mf++) {
                ldm_x4(ah[mf], SAh + aoff + mf * 2304u + kk * 32u);
                ldm_x4(al[mf], SAl + aoff + mf * 2304u + kk * 32u);
            }
            #pragma unroll
            for (int nf = 0; nf < 4; nf++) {
                uint32_t bh[2] = { bb[p][nf].x, bb[p][nf].y };
                uint32_t bl[2] = { bb[p][nf].z, bb[p][nf].w };
                #pragma unroll
                for (int mf = 0; mf < 2; mf++) {
                    mma16816(C[mf][nf], ah[mf], bh);
                    mma16816(C[mf][nf], ah[mf], bl);
                    mma16816(C[mf][nf], al[mf], bh);
                }
            }
        }

        // epilogue: +b1, relu, split, store rows owned by g
        #pragma unroll
        for (int mf = 0; mf < 2; mf++)
            #pragma unroll
            for (int half = 0; half < 2; half++) {
                int r = m_base + mf * 16 + (lane >> 2) + half * 8;
                if (sidx[r] == g) {
                    size_t base = (size_t)(b0 + r) * KP;
                    #pragma unroll
                    for (int nf = 0; nf < 4; nf++) {
                        int lc = n_base + nf * 8 + 2 * (lane & 3);
                        int n = n0 + lc;
                        if (n < H1D) {
                            float v0 = fmaxf(C[mf][nf][half * 2 + 0] + sb1[lc], 0.f);
                            float v1 = fmaxf(C[mf][nf][half * 2 + 1] + sb1[lc + 1], 0.f);
                            uint32_t h, l;
                            split2(v0, v1, h, l);
                            *(uint32_t*)(g_h1hi + base + n) = h;
                            *(uint32_t*)(g_h1lo + base + n) = l;
                        }
                    }
                }
            }
        __syncthreads();
    }
}

// ========== GEMM2: M=128 x N=64, CK=64; warp tile 16x64 (mf=1, nf=8) ==========
__global__ __launch_bounds__(256, 2) void h2q_mma_kernel(const int* __restrict__ idx,
                                                         const float* __restrict__ b2s,
                                                         const float* __restrict__ W3,
                                                         float* __restrict__ out) {
    extern __shared__ char dsm[];
    const uint32_t sbase = smem_u32(dsm);
    float* sb2 = (float*)(dsm + 2 * ASTAGE);
    float* sw3 = sb2 + 64;
    int* sidx = (int*)(sw3 + 64);
    const int tid = threadIdx.x, lane = tid & 31, wid = tid >> 5;
    const int n0 = blockIdx.x * 64, b0 = blockIdx.y * 128;
    if (tid < 128) sidx[tid] = idx[b0 + tid];
    if (tid < 64) { int n = n0 + tid; sb2[tid] = (n < H2D) ? b2s[n] : 0.f; }
    __syncthreads();
    const int g_lo = sidx[0], g_hi = sidx[127];
    const int m_base = wid * 16;                    // 8 warps cover M=128
    const uint32_t aoff = (uint32_t)(m_base + (lane & 15)) * ROWB + (uint32_t)((lane >> 4) * 16);
    const int ngbase = n0 >> 3;                     // all warps cover all 64 cols

    for (int g = g_lo; g <= g_hi; ++g) {
        if (tid < 64) { int n = n0 + tid; sw3[tid] = (n < H2D) ? W3[(size_t)g * H2D + n] : 0.f; }

        auto issueA = [&](int kc, int s) {
            #pragma unroll
            for (int i = 0; i < 8; i++) {
                int bid = tid + i * 256;
                int arr = bid >> 10, rem = bid & 1023;
                int row = rem >> 3, q = rem & 7;
                const __nv_bfloat16* src = (arr ? g_h1lo : g_h1hi) + (size_t)(b0 + row) * KP + kc * 64 + q * 8;
                cp16(sbase + (uint32_t)s * ASTAGE + (uint32_t)arr * AHALF + row * ROWB + q * 16u, src);
            }
            cp_commit();
        };
        auto loadB = [&](uint4 (&bb)[8], int kc, int kk) {
            const uint4* src;
            size_t base;
            if (kc < 9) {
                base = (size_t)((kc * 4 + kk) * 64 + ngbase) * 32 + lane;
                src = (const uint4*)g_W2f;
            } else {
                base = (size_t)((g * 4 + kk) * 64 + ngbase) * 32 + lane;
                src = (const uint4*)g_Btf;
            }
            #pragma unroll
            for (int nf = 0; nf < 8; nf++)
                bb[nf] = __ldg(src + base + (size_t)nf * 32);
        };

        float C[8][4];
        #pragma unroll
        for (int nf = 0; nf < 8; nf++)
            #pragma unroll
            for (int e = 0; e < 4; e++) C[nf][e] = 0.f;

        uint4 bb[2][8];
        loadB(bb[0], 0, 0);
        issueA(0, 0);
        for (int kc = 0; kc < 10; ++kc) {
            cp_wait0();
            __syncthreads();
            if (kc < 9) issueA(kc + 1, (kc + 1) & 1);
            const uint32_t SA = sbase + (uint32_t)(kc & 1) * ASTAGE;
            const uint32_t SAh = SA, SAl = SA + AHALF;
            #pragma unroll
            for (int kk = 0; kk < 4; kk++) {
                const int p = kk & 1;
                if (kk < 3)      loadB(bb[p ^ 1], kc, kk + 1);
                else if (kc < 9) loadB(bb[p ^ 1], kc + 1, 0);
                uint32_t ah[4], al[4];
                ldm_x4(ah, SAh + aoff + kk * 32u);
                ldm_x4(al, SAl + aoff + kk * 32u);
                #pragma unroll
                for (int nf = 0; nf < 8; nf++) {
                    uint32_t bh[2] = { bb[p][nf].x, bb[p][nf].y };
                    uint32_t bl[2] = { bb[p][nf].z, bb[p][nf].w };
                    mma16816(C[nf], ah, bh);
                    mma16816(C[nf], ah, bl);
                    mma16816(C[nf], al, bh);
                }
            }
        }

        // epilogue: relu(+b2s) . W3, quad-reduce, atomicAdd (one per row per CTA)
        #pragma unroll
        for (int half = 0; half < 2; half++) {
            int r = m_base + (lane >> 2) + half * 8;
            float qp = 0.f;
            #pragma unroll
            for (int nf = 0; nf < 8; nf++) {
                int lc = nf * 8 + 2 * (lane & 3);
                qp += fmaxf(C[nf][half * 2 + 0] + sb2[lc], 0.f) * sw3[lc];
                qp += fmaxf(C[nf][half * 2 + 1] + sb2[lc + 1], 0.f) * sw3[lc + 1];
            }
            qp += __shfl_xor_sync(0xffffffffu, qp, 1);
            qp += __shfl_xor_sync(0xffffffffu, qp, 2);
            if ((lane & 3) == 0 && sidx[r] == g) atomicAdd(out + b0 + r, qp);
        }
        __syncthreads();
    }
}

extern "C" void kernel_launch(void* const* d_in, const int* in_sizes, int n_in,
                              void* d_out, int out_size) {
    const float* state  = (const float*)d_in[0];
    const float* action = (const float*)d_in[1];
    const int*   idx    = (const int*)d_in[2];
    const float* W1     = (const float*)d_in[3];
    const float* b1     = (const float*)d_in[4];
    const float* W2s    = (const float*)d_in[5];
    const float* b2s    = (const float*)d_in[6];
    const float* W2a    = (const float*)d_in[7];
    const float* W3     = (const float*)d_in[8];
    const float* b3     = (const float*)d_in[9];
    float* out = (float*)d_out;

    cudaFuncSetAttribute(h1_mma_kernel,  cudaFuncAttributeMaxDynamicSharedMemorySize, GEMM_SMEM);
    cudaFuncSetAttribute(h2q_mma_kernel, cudaFuncAttributeMaxDynamicSharedMemorySize, GEMM_SMEM);

    prep_kernel<<<PREP_BLOCKS, 256>>>(state, action, idx, W1, W2s, W2a, b3, out);
    h1_mma_kernel<<<dim3(10, B_TOT / 128), 256, GEMM_SMEM>>>(idx, b1);
    h2q_mma_kernel<<<dim3(8, B_TOT / 128), 256, GEMM_SMEM>>>(idx, b2s, W3, out);
}

// round 14
// speedup vs baseline: 1.2559x; 1.2559x over previous
#include <cuda_runtime.h>
#include <cuda_bf16.h>
#include <cstdint>
#include <cstddef>

#define B_TOT 32768
#define D_IN  128
#define A_DIM 16
#define H1D   600
#define H2D   500
#define KP    640
#define G_N   8

// ---- h1 geometry (R10-proven) ----
#define H1_ROWB   144u
#define H1_AHALF  18432u
#define H1_BHALF  9216u
#define H1_STAGE  (2u*H1_AHALF + 2u*H1_BHALF)   // 55296
#define H1_SMEM   (2*H1_STAGE + 1024)

// ---- h2q geometry: A 2-stage smem + B fragment 2-stage smem ----
#define ROWB    144u
#define AHALF   18432u
#define ASTAGE  (2u*AHALF)          // 36864
#define BSTG    16384u              // 16KB of B fragments per chunk
#define H2_BOFF (2u*ASTAGE)        // 73728
#define H2_SMEM (2*ASTAGE + 2*BSTG + 1024)   // 107520

// ---- persistent device scratch ----
__device__ __nv_bfloat16 g_h1hi[(size_t)B_TOT * KP];
__device__ __nv_bfloat16 g_h1lo[(size_t)B_TOT * KP];
__device__ __nv_bfloat16 g_Sh[(size_t)B_TOT * D_IN];
__device__ __nv_bfloat16 g_Sl[(size_t)B_TOT * D_IN];
__device__ __nv_bfloat16 g_W1h[(size_t)G_N * 640 * D_IN];
__device__ __nv_bfloat16 g_W1l[(size_t)G_N * 640 * D_IN];
// B fragments: unit = ((kstep*64 + n8)*2 + h)*32 + lane, 8B each (b0|b1<<32)
__device__ uint64_t g_W2f[(size_t)36 * 64 * 2 * 32];
__device__ uint64_t g_Btf[(size_t)G_N * 4 * 64 * 2 * 32];

// ---------------- helpers ----------------
__device__ __forceinline__ uint32_t smem_u32(const void* p) {
    uint32_t a;
    asm("{ .reg .u64 t; cvta.to.shared.u64 t, %1; cvt.u32.u64 %0, t; }" : "=r"(a) : "l"(p));
    return a;
}
__device__ __forceinline__ void ldm_x4(uint32_t* r, uint32_t addr) {
    asm volatile("ldmatrix.sync.aligned.m8n8.x4.shared.b16 {%0,%1,%2,%3}, [%4];"
                 : "=r"(r[0]), "=r"(r[1]), "=r"(r[2]), "=r"(r[3]) : "r"(addr));
}
__device__ __forceinline__ void mma16816(float* c, const uint32_t* a, const uint32_t* b) {
    asm volatile("mma.sync.aligned.m16n8k16.row.col.f32.bf16.bf16.f32 "
                 "{%0,%1,%2,%3}, {%4,%5,%6,%7}, {%8,%9}, {%0,%1,%2,%3};"
                 : "+f"(c[0]), "+f"(c[1]), "+f"(c[2]), "+f"(c[3])
                 : "r"(a[0]), "r"(a[1]), "r"(a[2]), "r"(a[3]), "r"(b[0]), "r"(b[1]));
}
__device__ __forceinline__ void cp16(uint32_t dst, const void* src) {
    asm volatile("cp.async.cg.shared.global [%0], [%1], 16;" :: "r"(dst), "l"(src) : "memory");
}
__device__ __forceinline__ void cp_commit() { asm volatile("cp.async.commit_group;" ::: "memory"); }
__device__ __forceinline__ void cp_wait0() { asm volatile("cp.async.wait_group 0;" ::: "memory"); }
__device__ __forceinline__ void lds64(uint32_t& a, uint32_t& b, uint32_t addr) {
    asm volatile("ld.shared.v2.u32 {%0,%1}, [%2];" : "=r"(a), "=r"(b) : "r"(addr));
}

__device__ __forceinline__ uint32_t pack2(float f0, float f1) {
    uint32_t r;
    asm("cvt.rn.bf16x2.f32 %0, %1, %2;" : "=r"(r) : "f"(f1), "f"(f0));
    return r;
}
__device__ __forceinline__ void split2(float f0, float f1, uint32_t& h, uint32_t& l) {
    h = pack2(f0, f1);
    float h0 = __uint_as_float(h << 16);
    float h1 = __uint_as_float(h & 0xffff0000u);
    l = pack2(f0 - h0, f1 - h1);
}
__device__ __forceinline__ void split8(float4 v0, float4 v1, uint4& H, uint4& L) {
    split2(v0.x, v0.y, H.x, L.x);
    split2(v0.z, v0.w, H.y, L.y);
    split2(v1.x, v1.y, H.z, L.z);
    split2(v1.z, v1.w, H.w, L.w);
}

// ---------------- fused prep kernel (R10-proven) ----------------
// [0,128) init_out | [128,256) fill_pad | [256,2304) split_state | [2304,2624) split_W1
// [2624,2912) W2 frags | [2912,3168) Btail frags
#define PREP_BLOCKS 3168
__global__ __launch_bounds__(256) void prep_kernel(const float* __restrict__ state,
                                                   const float* __restrict__ action,
                                                   const int* __restrict__ idx,
                                                   const float* __restrict__ W1,
                                                   const float* __restrict__ W2s,
                                                   const float* __restrict__ W2a,
                                                   const float* __restrict__ b3,
                                                   float* __restrict__ out) {
    const int blk = blockIdx.x;
    const int t = threadIdx.x;
    if (blk < 128) {
        int i = blk * 256 + t;
        out[i] = b3[idx[i]];
    } else if (blk < 256) {
        int b = (blk - 128) * 256 + t;
        const float4* a4 = (const float4*)(action + (size_t)b * A_DIM);
        uint4 H0, L0, H1, L1;
        split8(a4[0], a4[1], H0, L0);
        split8(a4[2], a4[3], H1, L1);
        uint16_t* ph = (uint16_t*)g_h1hi + (size_t)b * KP + 600;
        uint16_t* pl = (uint16_t*)g_h1lo + (size_t)b * KP + 600;
        ((uint4*)ph)[0] = H0; ((uint4*)ph)[1] = H1;
        ((uint4*)pl)[0] = L0; ((uint4*)pl)[1] = L1;
        uint4 z = make_uint4(0, 0, 0, 0);
        ((uint4*)(ph + 16))[0] = z; ((uint4*)(ph + 16))[1] = z; ((uint4*)(ph + 16))[2] = z;
        ((uint4*)(pl + 16))[0] = z; ((uint4*)(pl + 16))[1] = z; ((uint4*)(pl + 16))[2] = z;
    } else if (blk < 2304) {
        size_t e = ((size_t)(blk - 256) * 256 + t) * 8;
        const float4* s4 = (const float4*)(state + e);
        uint4 H, L;
        split8(s4[0], s4[1], H, L);
        *(uint4*)((uint16_t*)g_Sh + e) = H;
        *(uint4*)((uint16_t*)g_Sl + e) = L;
    } else if (blk < 2624) {
        size_t e = ((size_t)(blk - 2304) * 256 + t) * 8;
        int g = (int)(e / (640 * D_IN));
        int r = (int)((e / D_IN) % 640);
        int c = (int)(e % D_IN);
        uint4 H = make_uint4(0, 0, 0, 0), L = H;
        if (r < H1D) {
            const float4* s4 = (const float4*)(W1 + ((size_t)g * H1D + r) * D_IN + c);
            split8(s4[0], s4[1], H, L);
        }
        *(uint4*)((uint16_t*)g_W1h + e) = H;
        *(uint4*)((uint16_t*)g_W1l + e) = L;
    } else if (blk < 2912) {
        int u = (blk - 2624) * 256 + t;     // [0, 73728)
        int lane = u & 31;
        int n8 = (u >> 5) & 63;
        int kq = u >> 11;
        int n = n8 * 8 + (lane >> 2);
        int k0 = kq * 16 + (lane & 3) * 2;
        float x0 = 0.f, x1 = 0.f, x2 = 0.f, x3 = 0.f;
        if (n < H2D) {
            const float* w = W2s + (size_t)n * H1D;
            x0 = w[k0]; x1 = w[k0 + 1]; x2 = w[k0 + 8]; x3 = w[k0 + 9];
        }
        uint32_t h0, l0, h1, l1;
        split2(x0, x1, h0, l0);
        split2(x2, x3, h1, l1);
        size_t base = ((size_t)(kq * 64 + n8) * 2) * 32 + lane;
        g_W2f[base]      = (uint64_t)h0 | ((uint64_t)h1 << 32);
        g_W2f[base + 32] = (uint64_t)l0 | ((uint64_t)l1 << 32);
    } else {
        int u = (blk - 2912) * 256 + t;     // [0, 65536)
        int lane = u & 31;
        int n8 = (u >> 5) & 63;
        int gk = u >> 11;
        int g = gk >> 2, kk = gk & 3;
        int n = n8 * 8 + (lane >> 2);
        int c0 = kk * 16 + (lane & 3) * 2;
        float v[4];
        const int off[4] = {0, 1, 8, 9};
        #pragma unroll
        for (int j = 0; j < 4; j++) {
            int tc = 576 + c0 + off[j];
            float x = 0.f;
            if (n < H2D) {
                if (tc < H1D) x = W2s[(size_t)n * H1D + tc];
                else if (tc < H1D + A_DIM) x = W2a[((size_t)g * H2D + n) * A_DIM + (tc - H1D)];
            }
            v[j] = x;
        }
        uint32_t h0, l0, h1, l1;
        split2(v[0], v[1], h0, l0);
        split2(v[2], v[3], h1, l1);
        size_t base = ((size_t)(gk * 64 + n8) * 2) * 32 + lane;
        g_Btf[base]      = (uint64_t)h0 | ((uint64_t)h1 << 32);
        g_Btf[base + 32] = (uint64_t)l0 | ((uint64_t)l1 << 32);
    }
}

// ================= GEMM1 (R10-proven): M=128,N=64,K=128, CK=64, 2 stages =================
#define MMA_STAGE1(sbase, s)                                                       \
    {                                                                              \
        const uint32_t SA = (sbase) + (uint32_t)(s) * H1_STAGE;                    \
        const uint32_t SAh = SA, SAl = SA + H1_AHALF;                              \
        const uint32_t SBh = SA + 2u * H1_AHALF, SBl = SBh + H1_BHALF;             \
        _Pragma("unroll")                                                          \
        for (int kk = 0; kk < 4; kk++) {                                           \
            uint32_t ah[2][4], al[2][4], bh[4][2], bl[4][2];                       \
            _Pragma("unroll")                                                      \
            for (int mf = 0; mf < 2; mf++) {                                       \
                ldm_x4(ah[mf], SAh + aoff + mf * 2304u + kk * 32u);                \
                ldm_x4(al[mf], SAl + aoff + mf * 2304u + kk * 32u);                \
            }                                                                      \
            _Pragma("unroll")                                                      \
            for (int nq = 0; nq < 2; nq++) {                                       \
                uint32_t t[4];                                                     \
                ldm_x4(t, SBh + boff + nq * 2304u + kk * 32u);                     \
                bh[nq * 2][0] = t[0]; bh[nq * 2][1] = t[2];                        \
                bh[nq * 2 + 1][0] = t[1]; bh[nq * 2 + 1][1] = t[3];                \
                ldm_x4(t, SBl + boff + nq * 2304u + kk * 32u);                     \
                bl[nq * 2][0] = t[0]; bl[nq * 2][1] = t[2];                        \
                bl[nq * 2 + 1][0] = t[1]; bl[nq * 2 + 1][1] = t[3];                \
            }                                                                      \
            _Pragma("unroll")                                                      \
            for (int mf = 0; mf < 2; mf++)                                         \
                _Pragma("unroll")                                                  \
                for (int nf = 0; nf < 4; nf++) {                                   \
                    mma16816(C[mf][nf], ah[mf], bh[nf]);                           \
                    mma16816(C[mf][nf], ah[mf], bl[nf]);                           \
                    mma16816(C[mf][nf], al[mf], bh[nf]);                           \
                }                                                                  \
        }                                                                          \
    }

__global__ __launch_bounds__(256, 2) void h1_mma_kernel(const int* __restrict__ idx,
                                                        const float* __restrict__ b1) {
    extern __shared__ char dsm[];
    const uint32_t sbase = smem_u32(dsm);
    float* sb1 = (float*)(dsm + 2 * H1_STAGE);
    int* sidx = (int*)(sb1 + 64);
    const int tid = threadIdx.x, lane = tid & 31, wid = tid >> 5;
    const int n0 = blockIdx.x * 64, b0 = blockIdx.y * 128;
    if (tid < 128) sidx[tid] = idx[b0 + tid];
    __syncthreads();
    const int g_lo = sidx[0], g_hi = sidx[127];
    const int m_base = (wid >> 1) * 32, n_base = (wid & 1) * 32;
    const uint32_t aoff = (uint32_t)(m_base + (lane & 15)) * H1_ROWB + (uint32_t)((lane >> 4) * 16);
    const uint32_t boff = (uint32_t)(n_base + (lane & 15)) * H1_ROWB + (uint32_t)((lane >> 4) * 16);

    for (int g = g_lo; g <= g_hi; ++g) {
        if (tid < 64) { int n = n0 + tid; sb1[tid] = (n < H1D) ? b1[(size_t)g * H1D + n] : 0.f; }
        auto issue = [&](int kc, int s) {
            #pragma unroll
            for (int i = 0; i < 8; i++) {
                int bid = tid + i * 256;
                int arr = bid >> 10, rem = bid & 1023;
                int row = rem >> 3, q = rem & 7;
                const __nv_bfloat16* src = (arr ? g_Sl : g_Sh) + (size_t)(b0 + row) * D_IN + kc * 64 + q * 8;
                cp16(sbase + (uint32_t)s * H1_STAGE + (uint32_t)arr * H1_AHALF + row * H1_ROWB + q * 16u, src);
            }
            #pragma unroll
            for (int i = 0; i < 4; i++) {
                int bid = tid + i * 256;
                int arr = bid >> 9, rem = bid & 511;
                int row = rem >> 3, q = rem & 7;
                const __nv_bfloat16* src = (arr ? g_W1l : g_W1h) + ((size_t)g * 640 + n0 + row) * D_IN + kc * 64 + q * 8;
                cp16(sbase + (uint32_t)s * H1_STAGE + 2u * H1_AHALF + (uint32_t)arr * H1_BHALF + row * H1_ROWB + q * 16u, src);
            }
            cp_commit();
        };
        float C[2][4][4];
        #pragma unroll
        for (int mf = 0; mf < 2; mf++)
            #pragma unroll
            for (int nf = 0; nf < 4; nf++)
                #pragma unroll
                for (int e = 0; e < 4; e++) C[mf][nf][e] = 0.f;

        issue(0, 0);
        cp_wait0();
        __syncthreads();
        issue(1, 1);
        MMA_STAGE1(sbase, 0);
        cp_wait0();
        __syncthreads();
        MMA_STAGE1(sbase, 1);

        #pragma unroll
        for (int mf = 0; mf < 2; mf++)
            #pragma unroll
            for (int half = 0; half < 2; half++) {
                int r = m_base + mf * 16 + (lane >> 2) + half * 8;
                if (sidx[r] == g) {
                    size_t base = (size_t)(b0 + r) * KP;
                    #pragma unroll
                    for (int nf = 0; nf < 4; nf++) {
                        int lc = n_base + nf * 8 + 2 * (lane & 3);
                        int n = n0 + lc;
                        if (n < H1D) {
                            float v0 = fmaxf(C[mf][nf][half * 2 + 0] + sb1[lc], 0.f);
                            float v1 = fmaxf(C[mf][nf][half * 2 + 1] + sb1[lc + 1], 0.f);
                            uint32_t h, l;
                            split2(v0, v1, h, l);
                            *(uint32_t*)(g_h1hi + base + n) = h;
                            *(uint32_t*)(g_h1lo + base + n) = l;
                        }
                    }
                }
            }
        __syncthreads();
    }
}

// ========== GEMM2: M=128 x N=64, CK=64; A cp.async+LDSM, B fragments staged via smem ==========
__global__ __launch_bounds__(256, 2) void h2q_mma_kernel(const int* __restrict__ idx,
                                                         const float* __restrict__ b2s,
                                                         const float* __restrict__ W3,
                                                         float* __restrict__ out) {
    extern __shared__ char dsm[];
    const uint32_t sbase = smem_u32(dsm);
    float* sb2 = (float*)(dsm + 2 * ASTAGE + 2 * BSTG);
    float* sw3 = sb2 + 64;
    int* sidx = (int*)(sw3 + 64);
    const int tid = threadIdx.x, lane = tid & 31, wid = tid >> 5;
    const int n0 = blockIdx.x * 64, b0 = blockIdx.y * 128;
    if (tid < 128) sidx[tid] = idx[b0 + tid];
    if (tid < 64) { int n = n0 + tid; sb2[tid] = (n < H2D) ? b2s[n] : 0.f; }
    __syncthreads();
    const int g_lo = sidx[0], g_hi = sidx[127];
    const int m_base = (wid >> 1) * 32;
    const int nhalf = wid & 1;                     // warp's 32-col half
    const uint32_t aoff = (uint32_t)(m_base + (lane & 15)) * ROWB + (uint32_t)((lane >> 4) * 16);
    const int ng0 = n0 >> 3;                       // CTA's first n8 unit

    for (int g = g_lo; g <= g_hi; ++g) {
        if (tid < 64) { int n = n0 + tid; sw3[tid] = (n < H2D) ? W3[(size_t)g * H2D + n] : 0.f; }

        // issue chunk kc: A (8x cp16) + B fragments (4x cp16) in one group
        auto issue = [&](int kc, int s) {
            #pragma unroll
            for (int i = 0; i < 8; i++) {
                int bid = tid + i * 256;
                int arr = bid >> 10, rem = bid & 1023;
                int row = rem >> 3, q = rem & 7;
                const __nv_bfloat16* src = (arr ? g_h1lo : g_h1hi) + (size_t)(b0 + row) * KP + kc * 64 + q * 8;
                cp16(sbase + (uint32_t)s * ASTAGE + (uint32_t)arr * AHALF + row * ROWB + q * 16u, src);
            }
            const char* bsrc = (kc < 9) ? (const char*)g_W2f : (const char*)g_Btf;
            #pragma unroll
            for (int i = 0; i < 4; i++) {
                int bid = tid + i * 256;       // [0,1024): kk = bid>>8, w = bid&255 (16B units)
                int kk = bid >> 8, w = bid & 255;
                size_t goff = (kc < 9)
                    ? ((size_t)((kc * 4 + kk) * 64 + ng0) * 512 + (size_t)w * 16)
                    : ((size_t)((g  * 4 + kk) * 64 + ng0) * 512 + (size_t)w * 16);
                cp16(sbase + H2_BOFF + (uint32_t)s * BSTG + (uint32_t)kk * 4096u + (uint32_t)w * 16u,
                     bsrc + goff);
            }
            cp_commit();
        };
        // read B fragments for one kk from smem (conflict-free LDS.64)
        auto ldsB = [&](uint32_t (&bb)[4][2][2], uint32_t Bkk) {
            #pragma unroll
            for (int nf = 0; nf < 4; nf++)
                #pragma unroll
                for (int h = 0; h < 2; h++) {
                    uint32_t addr = Bkk + (uint32_t)(((nhalf * 4 + nf) * 2 + h) * 256) + (uint32_t)lane * 8u;
                    lds64(bb[nf][h][0], bb[nf][h][1], addr);
                }
        };

        float C[2][4][4];
        #pragma unroll
        for (int mf = 0; mf < 2; mf++)
            #pragma unroll
            for (int nf = 0; nf < 4; nf++)
                #pragma unroll
                for (int e = 0; e < 4; e++) C[mf][nf][e] = 0.f;

        issue(0, 0);
        for (int kc = 0; kc < 10; ++kc) {
            cp_wait0();
            __syncthreads();
            if (kc < 9) issue(kc + 1, (kc + 1) & 1);
            const uint32_t SA = sbase + (uint32_t)(kc & 1) * ASTAGE;
            const uint32_t SAh = SA, SAl = SA + AHALF;
            const uint32_t Bs = sbase + H2_BOFF + (uint32_t)(kc & 1) * BSTG;
            uint32_t bb[2][4][2][2];
            ldsB(bb[0], Bs);
            #pragma unroll
            for (int kk = 0; kk < 4; kk++) {
                const int p = kk & 1;
                if (kk < 3) ldsB(bb[p ^ 1], Bs + (uint32_t)(kk + 1) * 4096u);
                uint32_t ah[2][4], al[2][4];
                #pragma unroll
                for (int mf = 0; mf < 2; mf++) {
                    ldm_x4(ah[mf], SAh + aoff + mf * 2304u + kk * 32u);
                    ldm_x4(al[mf], SAl + aoff + mf * 2304u + kk * 32u);
                }
                #pragma unroll
                for (int mf = 0; mf < 2; mf++)
                    #pragma unroll
                    for (int nf = 0; nf < 4; nf++) {
                        mma16816(C[mf][nf], ah[mf], bb[p][nf][0]);
                        mma16816(C[mf][nf], ah[mf], bb[p][nf][1]);
                        mma16816(C[mf][nf], al[mf], bb[p][nf][0]);
                    }
            }
        }

        // epilogue: relu(+b2s) . W3, quad-reduce, atomicAdd
        #pragma unroll
        for (int mf = 0; mf < 2; mf++)
            #pragma unroll
            for (int half = 0; half < 2; half++) {
                int r = m_base + mf * 16 + (lane >> 2) + half * 8;
                float qp = 0.f;
                #pragma unroll
                for (int nf = 0; nf < 4; nf++) {
                    int lc = nhalf * 32 + nf * 8 + 2 * (lane & 3);
                    qp += fmaxf(C[mf][nf][half * 2 + 0] + sb2[lc], 0.f) * sw3[lc];
                    qp += fmaxf(C[mf][nf][half * 2 + 1] + sb2[lc + 1], 0.f) * sw3[lc + 1];
                }
                qp += __shfl_xor_sync(0xffffffffu, qp, 1);
                qp += __shfl_xor_sync(0xffffffffu, qp, 2);
                if ((lane & 3) == 0 && sidx[r] == g) atomicAdd(out + b0 + r, qp);
            }
        __syncthreads();
    }
}

extern "C" void kernel_launch(void* const* d_in, const int* in_sizes, int n_in,
                              void* d_out, int out_size) {
    const float* state  = (const float*)d_in[0];
    const float* action = (const float*)d_in[1];
    const int*   idx    = (const int*)d_in[2];
    const float* W1     = (const float*)d_in[3];
    const float* b1     = (const float*)d_in[4];
    const float* W2s    = (const float*)d_in[5];
    const float* b2s    = (const float*)d_in[6];
    const float* W2a    = (const float*)d_in[7];
    const float* W3     = (const float*)d_in[8];
    const float* b3     = (const float*)d_in[9];
    float* out = (float*)d_out;

    cudaFuncSetAttribute(h1_mma_kernel,  cudaFuncAttributeMaxDynamicSharedMemorySize, H1_SMEM);
    cudaFuncSetAttribute(h2q_mma_kernel, cudaFuncAttributeMaxDynamicSharedMemorySize, H2_SMEM);

    prep_kernel<<<PREP_BLOCKS, 256>>>(state, action, idx, W1, W2s, W2a, b3, out);
    h1_mma_kernel<<<dim3(10, B_TOT / 128), 256, H1_SMEM>>>(idx, b1);
    h2q_mma_kernel<<<dim3(8, B_TOT / 128), 256, H2_SMEM>>>(idx, b2s, W3, out);
}

// round 15
// speedup vs baseline: 1.2604x; 1.0036x over previous
#include <cuda_runtime.h>
#include <cuda_bf16.h>
#include <cstdint>
#include <cstddef>

#define B_TOT 32768
#define D_IN  128
#define A_DIM 16
#define H1D   600
#define H2D   500
#define KP    640
#define G_N   8

// ---- h1 geometry (R10-proven) ----
#define H1_ROWB   144u
#define H1_AHALF  18432u
#define H1_BHALF  9216u
#define H1_STAGE  (2u*H1_AHALF + 2u*H1_BHALF)   // 55296
#define H1_SMEM   (2*H1_STAGE + 1024)           // 111616

// ---- h2q geometry (R14-proven): A 2-stage smem + B fragment 2-stage smem ----
#define ROWB    144u
#define AHALF   18432u
#define ASTAGE  (2u*AHALF)          // 36864
#define BSTG    16384u
#define H2_BOFF (2u*ASTAGE)         // 73728
#define H2_SMEM (2*ASTAGE + 2*BSTG + 1024)   // 107520

#define FUSED_SMEM (H1_SMEM > H2_SMEM ? H1_SMEM : H2_SMEM)

// ---- persistent device scratch ----
__device__ __nv_bfloat16 g_h1hi[(size_t)B_TOT * KP];
__device__ __nv_bfloat16 g_h1lo[(size_t)B_TOT * KP];
__device__ __nv_bfloat16 g_Sh[(size_t)B_TOT * D_IN];
__device__ __nv_bfloat16 g_Sl[(size_t)B_TOT * D_IN];
__device__ __nv_bfloat16 g_W1h[(size_t)G_N * 640 * D_IN];
__device__ __nv_bfloat16 g_W1l[(size_t)G_N * 640 * D_IN];
__device__ uint64_t g_W2f[(size_t)36 * 64 * 2 * 32];
__device__ uint64_t g_Btf[(size_t)G_N * 4 * 64 * 2 * 32];
__device__ int g_done[256];   // per-b-block h1 completion counters (zeroed by prep)

// ---------------- helpers ----------------
__device__ __forceinline__ uint32_t smem_u32(const void* p) {
    uint32_t a;
    asm("{ .reg .u64 t; cvta.to.shared.u64 t, %1; cvt.u32.u64 %0, t; }" : "=r"(a) : "l"(p));
    return a;
}
__device__ __forceinline__ void ldm_x4(uint32_t* r, uint32_t addr) {
    asm volatile("ldmatrix.sync.aligned.m8n8.x4.shared.b16 {%0,%1,%2,%3}, [%4];"
                 : "=r"(r[0]), "=r"(r[1]), "=r"(r[2]), "=r"(r[3]) : "r"(addr));
}
__device__ __forceinline__ void mma16816(float* c, const uint32_t* a, const uint32_t* b) {
    asm volatile("mma.sync.aligned.m16n8k16.row.col.f32.bf16.bf16.f32 "
                 "{%0,%1,%2,%3}, {%4,%5,%6,%7}, {%8,%9}, {%0,%1,%2,%3};"
                 : "+f"(c[0]), "+f"(c[1]), "+f"(c[2]), "+f"(c[3])
                 : "r"(a[0]), "r"(a[1]), "r"(a[2]), "r"(a[3]), "r"(b[0]), "r"(b[1]));
}
__device__ __forceinline__ void cp16(uint32_t dst, const void* src) {
    asm volatile("cp.async.cg.shared.global [%0], [%1], 16;" :: "r"(dst), "l"(src) : "memory");
}
__device__ __forceinline__ void cp_commit() { asm volatile("cp.async.commit_group;" ::: "memory"); }
__device__ __forceinline__ void cp_wait0() { asm volatile("cp.async.wait_group 0;" ::: "memory"); }
__device__ __forceinline__ void lds64(uint32_t& a, uint32_t& b, uint32_t addr) {
    asm volatile("ld.shared.v2.u32 {%0,%1}, [%2];" : "=r"(a), "=r"(b) : "r"(addr));
}
__device__ __forceinline__ int ld_acquire(const int* p) {
    int v;
    asm volatile("ld.acquire.gpu.b32 %0, [%1];" : "=r"(v) : "l"(p) : "memory");
    return v;
}

__device__ __forceinline__ uint32_t pack2(float f0, float f1) {
    uint32_t r;
    asm("cvt.rn.bf16x2.f32 %0, %1, %2;" : "=r"(r) : "f"(f1), "f"(f0));
    return r;
}
__device__ __forceinline__ void split2(float f0, float f1, uint32_t& h, uint32_t& l) {
    h = pack2(f0, f1);
    float h0 = __uint_as_float(h << 16);
    float h1 = __uint_as_float(h & 0xffff0000u);
    l = pack2(f0 - h0, f1 - h1);
}
__device__ __forceinline__ void split8(float4 v0, float4 v1, uint4& H, uint4& L) {
    split2(v0.x, v0.y, H.x, L.x);
    split2(v0.z, v0.w, H.y, L.y);
    split2(v1.x, v1.y, H.z, L.z);
    split2(v1.z, v1.w, H.w, L.w);
}

// ---------------- fused prep kernel ----------------
// [0,128) init_out | [128,256) fill_pad | [256,2304) split_state | [2304,2624) split_W1
// [2624,2912) W2 frags | [2912,3168) Btail frags | [3168] zero g_done
#define PREP_BLOCKS 3169
__global__ __launch_bounds__(256) void prep_kernel(const float* __restrict__ state,
                                                   const float* __restrict__ action,
                                                   const int* __restrict__ idx,
                                                   const float* __restrict__ W1,
                                                   const float* __restrict__ W2s,
                                                   const float* __restrict__ W2a,
                                                   const float* __restrict__ b3,
                                                   float* __restrict__ out) {
    const int blk = blockIdx.x;
    const int t = threadIdx.x;
    if (blk < 128) {
        int i = blk * 256 + t;
        out[i] = b3[idx[i]];
    } else if (blk < 256) {
        int b = (blk - 128) * 256 + t;
        const float4* a4 = (const float4*)(action + (size_t)b * A_DIM);
        uint4 H0, L0, H1, L1;
        split8(a4[0], a4[1], H0, L0);
        split8(a4[2], a4[3], H1, L1);
        uint16_t* ph = (uint16_t*)g_h1hi + (size_t)b * KP + 600;
        uint16_t* pl = (uint16_t*)g_h1lo + (size_t)b * KP + 600;
        ((uint4*)ph)[0] = H0; ((uint4*)ph)[1] = H1;
        ((uint4*)pl)[0] = L0; ((uint4*)pl)[1] = L1;
        uint4 z = make_uint4(0, 0, 0, 0);
        ((uint4*)(ph + 16))[0] = z; ((uint4*)(ph + 16))[1] = z; ((uint4*)(ph + 16))[2] = z;
        ((uint4*)(pl + 16))[0] = z; ((uint4*)(pl + 16))[1] = z; ((uint4*)(pl + 16))[2] = z;
    } else if (blk < 2304) {
        size_t e = ((size_t)(blk - 256) * 256 + t) * 8;
        const float4* s4 = (const float4*)(state + e);
        uint4 H, L;
        split8(s4[0], s4[1], H, L);
        *(uint4*)((uint16_t*)g_Sh + e) = H;
        *(uint4*)((uint16_t*)g_Sl + e) = L;
    } else if (blk < 2624) {
        size_t e = ((size_t)(blk - 2304) * 256 + t) * 8;
        int g = (int)(e / (640 * D_IN));
        int r = (int)((e / D_IN) % 640);
        int c = (int)(e % D_IN);
        uint4 H = make_uint4(0, 0, 0, 0), L = H;
        if (r < H1D) {
            const float4* s4 = (const float4*)(W1 + ((size_t)g * H1D + r) * D_IN + c);
            split8(s4[0], s4[1], H, L);
        }
        *(uint4*)((uint16_t*)g_W1h + e) = H;
        *(uint4*)((uint16_t*)g_W1l + e) = L;
    } else if (blk < 2912) {
        int u = (blk - 2624) * 256 + t;
        int lane = u & 31;
        int n8 = (u >> 5) & 63;
        int kq = u >> 11;
        int n = n8 * 8 + (lane >> 2);
        int k0 = kq * 16 + (lane & 3) * 2;
        float x0 = 0.f, x1 = 0.f, x2 = 0.f, x3 = 0.f;
        if (n < H2D) {
            const float* w = W2s + (size_t)n * H1D;
            x0 = w[k0]; x1 = w[k0 + 1]; x2 = w[k0 + 8]; x3 = w[k0 + 9];
        }
        uint32_t h0, l0, h1, l1;
        split2(x0, x1, h0, l0);
        split2(x2, x3, h1, l1);
        size_t base = ((size_t)(kq * 64 + n8) * 2) * 32 + lane;
        g_W2f[base]      = (uint64_t)h0 | ((uint64_t)h1 << 32);
        g_W2f[base + 32] = (uint64_t)l0 | ((uint64_t)l1 << 32);
    } else if (blk < 3168) {
        int u = (blk - 2912) * 256 + t;
        int lane = u & 31;
        int n8 = (u >> 5) & 63;
        int gk = u >> 11;
        int g = gk >> 2, kk = gk & 3;
        int n = n8 * 8 + (lane >> 2);
        int c0 = kk * 16 + (lane & 3) * 2;
        float v[4];
        const int off[4] = {0, 1, 8, 9};
        #pragma unroll
        for (int j = 0; j < 4; j++) {
            int tc = 576 + c0 + off[j];
            float x = 0.f;
            if (n < H2D) {
                if (tc < H1D) x = W2s[(size_t)n * H1D + tc];
                else if (tc < H1D + A_DIM) x = W2a[((size_t)g * H2D + n) * A_DIM + (tc - H1D)];
            }
            v[j] = x;
        }
        uint32_t h0, l0, h1, l1;
        split2(v[0], v[1], h0, l0);
        split2(v[2], v[3], h1, l1);
        size_t base = ((size_t)(gk * 64 + n8) * 2) * 32 + lane;
        g_Btf[base]      = (uint64_t)h0 | ((uint64_t)h1 << 32);
        g_Btf[base + 32] = (uint64_t)l0 | ((uint64_t)l1 << 32);
    } else {
        g_done[t] = 0;  // t in [0,256)
    }
}

// ---------------- fused GEMM kernel ----------------
// blocks [0,2560): h1 tile, id = b_blk*10 + n_idx
// blocks [2560,4608): h2q tile, id-2560 = b_blk*8 + n_idx
#define MMA_STAGE1(sbase, s)                                                       \
    {                                                                              \
        const uint32_t SA = (sbase) + (uint32_t)(s) * H1_STAGE;                    \
        const uint32_t SAh = SA, SAl = SA + H1_AHALF;                              \
        const uint32_t SBh = SA + 2u * H1_AHALF, SBl = SBh + H1_BHALF;             \
        _Pragma("unroll")                                                          \
        for (int kk = 0; kk < 4; kk++) {                                           \
            uint32_t ah[2][4], al[2][4], bh[4][2], bl[4][2];                       \
            _Pragma("unroll")                                                      \
            for (int mf = 0; mf < 2; mf++) {                                       \
                ldm_x4(ah[mf], SAh + aoff + mf * 2304u + kk * 32u);                \
                ldm_x4(al[mf], SAl + aoff + mf * 2304u + kk * 32u);                \
            }                                                                      \
            _Pragma("unroll")                                                      \
            for (int nq = 0; nq < 2; nq++) {                                       \
                uint32_t t[4];                                                     \
                ldm_x4(t, SBh + boff + nq * 2304u + kk * 32u);                     \
                bh[nq * 2][0] = t[0]; bh[nq * 2][1] = t[2];                        \
                bh[nq * 2 + 1][0] = t[1]; bh[nq * 2 + 1][1] = t[3];                \
                ldm_x4(t, SBl + boff + nq * 2304u + kk * 32u);                     \
                bl[nq * 2][0] = t[0]; bl[nq * 2][1] = t[2];                        \
                bl[nq * 2 + 1][0] = t[1]; bl[nq * 2 + 1][1] = t[3];                \
            }                                                                      \
            _Pragma("unroll")                                                      \
            for (int mf = 0; mf < 2; mf++)                                         \
                _Pragma("unroll")                                                  \
                for (int nf = 0; nf < 4; nf++) {                                   \
                    mma16816(C[mf][nf], ah[mf], bh[nf]);                           \
                    mma16816(C[mf][nf], ah[mf], bl[nf]);                           \
                    mma16816(C[mf][nf], al[mf], bh[nf]);                           \
                }                                                                  \
        }                                                                          \
    }

__global__ __launch_bounds__(256, 2) void fused_mma_kernel(const int* __restrict__ idx,
                                                           const float* __restrict__ b1,
                                                           const float* __restrict__ b2s,
                                                           const float* __restrict__ W3,
                                                           float* __restrict__ out) {
    extern __shared__ char dsm[];
    const uint32_t sbase = smem_u32(dsm);
    const int tid = threadIdx.x, lane = tid & 31, wid = tid >> 5;

    if (blockIdx.x < 2560) {
        // ================= h1 tile =================
        const int b_blk = blockIdx.x / 10, n_idx = blockIdx.x % 10;
        const int n0 = n_idx * 64, b0 = b_blk * 128;
        float* sb1 = (float*)(dsm + 2 * H1_STAGE);
        int* sidx = (int*)(sb1 + 64);
        if (tid < 128) sidx[tid] = idx[b0 + tid];
        __syncthreads();
        const int g_lo = sidx[0], g_hi = sidx[127];
        const int m_base = (wid >> 1) * 32, n_base = (wid & 1) * 32;
        const uint32_t aoff = (uint32_t)(m_base + (lane & 15)) * H1_ROWB + (uint32_t)((lane >> 4) * 16);
        const uint32_t boff = (uint32_t)(n_base + (lane & 15)) * H1_ROWB + (uint32_t)((lane >> 4) * 16);

        for (int g = g_lo; g <= g_hi; ++g) {
            if (tid < 64) { int n = n0 + tid; sb1[tid] = (n < H1D) ? b1[(size_t)g * H1D + n] : 0.f; }
            auto issue = [&](int kc, int s) {
                #pragma unroll
                for (int i = 0; i < 8; i++) {
                    int bid = tid + i * 256;
                    int arr = bid >> 10, rem = bid & 1023;
                    int row = rem >> 3, q = rem & 7;
                    const __nv_bfloat16* src = (arr ? g_Sl : g_Sh) + (size_t)(b0 + row) * D_IN + kc * 64 + q * 8;
                    cp16(sbase + (uint32_t)s * H1_STAGE + (uint32_t)arr * H1_AHALF + row * H1_ROWB + q * 16u, src);
                }
                #pragma unroll
                for (int i = 0; i < 4; i++) {
                    int bid = tid + i * 256;
                    int arr = bid >> 9, rem = bid & 511;
                    int row = rem >> 3, q = rem & 7;
                    const __nv_bfloat16* src = (arr ? g_W1l : g_W1h) + ((size_t)g * 640 + n0 + row) * D_IN + kc * 64 + q * 8;
                    cp16(sbase + (uint32_t)s * H1_STAGE + 2u * H1_AHALF + (uint32_t)arr * H1_BHALF + row * H1_ROWB + q * 16u, src);
                }
                cp_commit();
            };
            float C[2][4][4];
            #pragma unroll
            for (int mf = 0; mf < 2; mf++)
                #pragma unroll
                for (int nf = 0; nf < 4; nf++)
                    #pragma unroll
                    for (int e = 0; e < 4; e++) C[mf][nf][e] = 0.f;

            issue(0, 0);
            cp_wait0();
            __syncthreads();
            issue(1, 1);
            MMA_STAGE1(sbase, 0);
            cp_wait0();
            __syncthreads();
            MMA_STAGE1(sbase, 1);

            #pragma unroll
            for (int mf = 0; mf < 2; mf++)
                #pragma unroll
                for (int half = 0; half < 2; half++) {
                    int r = m_base + mf * 16 + (lane >> 2) + half * 8;
                    if (sidx[r] == g) {
                        size_t base = (size_t)(b0 + r) * KP;
                        #pragma unroll
                        for (int nf = 0; nf < 4; nf++) {
                            int lc = n_base + nf * 8 + 2 * (lane & 3);
                            int n = n0 + lc;
                            if (n < H1D) {
                                float v0 = fmaxf(C[mf][nf][half * 2 + 0] + sb1[lc], 0.f);
                                float v1 = fmaxf(C[mf][nf][half * 2 + 1] + sb1[lc + 1], 0.f);
                                uint32_t h, l;
                                split2(v0, v1, h, l);
                                *(uint32_t*)(g_h1hi + base + n) = h;
                                *(uint32_t*)(g_h1lo + base + n) = l;
                            }
                        }
                    }
                }
            __syncthreads();
        }
        // publish h1 completion for this b-block
        __threadfence();
        __syncthreads();
        if (tid == 0) atomicAdd(&g_done[b_blk], 1);
    } else {
        // ================= h2q tile =================
        const int tix = blockIdx.x - 2560;
        const int b_blk = tix / 8, n_idx = tix % 8;
        const int n0 = n_idx * 64, b0 = b_blk * 128;
        float* sb2 = (float*)(dsm + 2 * ASTAGE + 2 * BSTG);
        float* sw3 = sb2 + 64;
        int* sidx = (int*)(sw3 + 64);
        if (tid < 128) sidx[tid] = idx[b0 + tid];
        if (tid < 64) { int n = n0 + tid; sb2[tid] = (n < H2D) ? b2s[n] : 0.f; }
        // wait for all 10 h1 tiles of this b-block
        if (tid == 0) {
            while (ld_acquire(&g_done[b_blk]) < 10) {}
        }
        __syncthreads();
        const int g_lo = sidx[0], g_hi = sidx[127];
        const int m_base = (wid >> 1) * 32;
        const int nhalf = wid & 1;
        const uint32_t aoff = (uint32_t)(m_base + (lane & 15)) * ROWB + (uint32_t)((lane >> 4) * 16);
        const int ng0 = n0 >> 3;

        for (int g = g_lo; g <= g_hi; ++g) {
            if (tid < 64) { int n = n0 + tid; sw3[tid] = (n < H2D) ? W3[(size_t)g * H2D + n] : 0.f; }

            auto issue = [&](int kc, int s) {
                #pragma unroll
                for (int i = 0; i < 8; i++) {
                    int bid = tid + i * 256;
                    int arr = bid >> 10, rem = bid & 1023;
                    int row = rem >> 3, q = rem & 7;
                    const __nv_bfloat16* src = (arr ? g_h1lo : g_h1hi) + (size_t)(b0 + row) * KP + kc * 64 + q * 8;
                    cp16(sbase + (uint32_t)s * ASTAGE + (uint32_t)arr * AHALF + row * ROWB + q * 16u, src);
                }
                const char* bsrc = (kc < 9) ? (const char*)g_W2f : (const char*)g_Btf;
                #pragma unroll
                for (int i = 0; i < 4; i++) {
                    int bid = tid + i * 256;
                    int kk = bid >> 8, w = bid & 255;
                    size_t goff = (kc < 9)
                        ? ((size_t)((kc * 4 + kk) * 64 + ng0) * 512 + (size_t)w * 16)
                        : ((size_t)((g  * 4 + kk) * 64 + ng0) * 512 + (size_t)w * 16);
                    cp16(sbase + H2_BOFF + (uint32_t)s * BSTG + (uint32_t)kk * 4096u + (uint32_t)w * 16u,
                         bsrc + goff);
                }
                cp_commit();
            };
            auto ldsB = [&](uint32_t (&bb)[4][2][2], uint32_t Bkk) {
                #pragma unroll
                for (int nf = 0; nf < 4; nf++)
                    #pragma unroll
                    for (int h = 0; h < 2; h++) {
                        uint32_t addr = Bkk + (uint32_t)(((nhalf * 4 + nf) * 2 + h) * 256) + (uint32_t)lane * 8u;
                        lds64(bb[nf][h][0], bb[nf][h][1], addr);
                    }
            };

            float C[2][4][4];
            #pragma unroll
            for (int mf = 0; mf < 2; mf++)
                #pragma unroll
                for (int nf = 0; nf < 4; nf++)
                    #pragma unroll
                    for (int e = 0; e < 4; e++) C[mf][nf][e] = 0.f;

            issue(0, 0);
            for (int kc = 0; kc < 10; ++kc) {
                cp_wait0();
                __syncthreads();
                if (kc < 9) issue(kc + 1, (kc + 1) & 1);
                const uint32_t SA = sbase + (uint32_t)(kc & 1) * ASTAGE;
                const uint32_t SAh = SA, SAl = SA + AHALF;
                const uint32_t Bs = sbase + H2_BOFF + (uint32_t)(kc & 1) * BSTG;
                uint32_t bb[2][4][2][2];
                ldsB(bb[0], Bs);
                #pragma unroll
                for (int kk = 0; kk < 4; kk++) {
                    const int p = kk & 1;
                    if (kk < 3) ldsB(bb[p ^ 1], Bs + (uint32_t)(kk + 1) * 4096u);
                    uint32_t ah[2][4], al[2][4];
                    #pragma unroll
                    for (int mf = 0; mf < 2; mf++) {
                        ldm_x4(ah[mf], SAh + aoff + mf * 2304u + kk * 32u);
                        ldm_x4(al[mf], SAl + aoff + mf * 2304u + kk * 32u);
                    }
                    #pragma unroll
                    for (int mf = 0; mf < 2; mf++)
                        #pragma unroll
                        for (int nf = 0; nf < 4; nf++) {
                            mma16816(C[mf][nf], ah[mf], bb[p][nf][0]);
                            mma16816(C[mf][nf], ah[mf], bb[p][nf][1]);
                            mma16816(C[mf][nf], al[mf], bb[p][nf][0]);
                        }
                }
            }

            #pragma unroll
            for (int mf = 0; mf < 2; mf++)
                #pragma unroll
                for (int half = 0; half < 2; half++) {
                    int r = m_base + mf * 16 + (lane >> 2) + half * 8;
                    float qp = 0.f;
                    #pragma unroll
                    for (int nf = 0; nf < 4; nf++) {
                        int lc = nhalf * 32 + nf * 8 + 2 * (lane & 3);
                        qp += fmaxf(C[mf][nf][half * 2 + 0] + sb2[lc], 0.f) * sw3[lc];
                        qp += fmaxf(C[mf][nf][half * 2 + 1] + sb2[lc + 1], 0.f) * sw3[lc + 1];
                    }
                    qp += __shfl_xor_sync(0xffffffffu, qp, 1);
                    qp += __shfl_xor_sync(0xffffffffu, qp, 2);
                    if ((lane & 3) == 0 && sidx[r] == g) atomicAdd(out + b0 + r, qp);
                }
            __syncthreads();
        }
    }
}

extern "C" void kernel_launch(void* const* d_in, const int* in_sizes, int n_in,
                              void* d_out, int out_size) {
    const float* state  = (const float*)d_in[0];
    const float* action = (const float*)d_in[1];
    const int*   idx    = (const int*)d_in[2];
    const float* W1     = (const float*)d_in[3];
    const float* b1     = (const float*)d_in[4];
    const float* W2s    = (const float*)d_in[5];
    const float* b2s    = (const float*)d_in[6];
    const float* W2a    = (const float*)d_in[7];
    const float* W3     = (const float*)d_in[8];
    const float* b3     = (const float*)d_in[9];
    float* out = (float*)d_out;

    cudaFuncSetAttribute(fused_mma_kernel, cudaFuncAttributeMaxDynamicSharedMemorySize, FUSED_SMEM);

    prep_kernel<<<PREP_BLOCKS, 256>>>(state, action, idx, W1, W2s, W2a, b3, out);
    fused_mma_kernel<<<4608, 256, FUSED_SMEM>>>(idx, b1, b2s, W3, out);
}

// round 16
// speedup vs baseline: 1.7045x; 1.3524x over previous
#include <cuda_runtime.h>
#include <cuda_bf16.h>
#include <cuda_fp16.h>
#include <cstdint>
#include <cstddef>

#define B_TOT 32768
#define D_IN  128
#define A_DIM 16
#define H1D   600
#define H2D   500
#define KP    640
#define G_N   8

// ---- h1 geometry (R10-proven, bf16 3-term) ----
#define H1_ROWB   144u
#define H1_AHALF  18432u
#define H1_BHALF  9216u
#define H1_STAGE  (2u*H1_AHALF + 2u*H1_BHALF)   // 55296
#define H1_SMEM   (2*H1_STAGE + 1024)           // 111616

// ---- h2q geometry: fp16 A (single) 2-stage + B fragment 2-stage ----
#define ROWB    144u
#define A2STG   18432u              // 128 rows x 144B, single fp16 half
#define BSTG    16384u
#define H2_BOFF (2u*A2STG)          // 36864
#define H2_SMEM (2*A2STG + 2*BSTG + 1024)   // 70656

#define FUSED_SMEM (H1_SMEM > H2_SMEM ? H1_SMEM : H2_SMEM)

// ---- persistent device scratch ----
__device__ __half     g_h1f[(size_t)B_TOT * KP];          // fp16 h1 activations (+action pad)
__device__ __nv_bfloat16 g_Sh[(size_t)B_TOT * D_IN];
__device__ __nv_bfloat16 g_Sl[(size_t)B_TOT * D_IN];
__device__ __nv_bfloat16 g_W1h[(size_t)G_N * 640 * D_IN];
__device__ __nv_bfloat16 g_W1l[(size_t)G_N * 640 * D_IN];
// B fragments (fp16 hi/lo): unit = ((kstep*64 + n8)*2 + h)*32 + lane, 8B each
__device__ uint64_t g_W2f[(size_t)36 * 64 * 2 * 32];
__device__ uint64_t g_Btf[(size_t)G_N * 4 * 64 * 2 * 32];
__device__ int g_done[256];

// ---------------- helpers ----------------
__device__ __forceinline__ uint32_t smem_u32(const void* p) {
    uint32_t a;
    asm("{ .reg .u64 t; cvta.to.shared.u64 t, %1; cvt.u32.u64 %0, t; }" : "=r"(a) : "l"(p));
    return a;
}
__device__ __forceinline__ void ldm_x4(uint32_t* r, uint32_t addr) {
    asm volatile("ldmatrix.sync.aligned.m8n8.x4.shared.b16 {%0,%1,%2,%3}, [%4];"
                 : "=r"(r[0]), "=r"(r[1]), "=r"(r[2]), "=r"(r[3]) : "r"(addr));
}
__device__ __forceinline__ void mma_bf16(float* c, const uint32_t* a, const uint32_t* b) {
    asm volatile("mma.sync.aligned.m16n8k16.row.col.f32.bf16.bf16.f32 "
                 "{%0,%1,%2,%3}, {%4,%5,%6,%7}, {%8,%9}, {%0,%1,%2,%3};"
                 : "+f"(c[0]), "+f"(c[1]), "+f"(c[2]), "+f"(c[3])
                 : "r"(a[0]), "r"(a[1]), "r"(a[2]), "r"(a[3]), "r"(b[0]), "r"(b[1]));
}
__device__ __forceinline__ void mma_f16(float* c, const uint32_t* a, const uint32_t* b) {
    asm volatile("mma.sync.aligned.m16n8k16.row.col.f32.f16.f16.f32 "
                 "{%0,%1,%2,%3}, {%4,%5,%6,%7}, {%8,%9}, {%0,%1,%2,%3};"
                 : "+f"(c[0]), "+f"(c[1]), "+f"(c[2]), "+f"(c[3])
                 : "r"(a[0]), "r"(a[1]), "r"(a[2]), "r"(a[3]), "r"(b[0]), "r"(b[1]));
}
__device__ __forceinline__ void cp16(uint32_t dst, const void* src) {
    asm volatile("cp.async.cg.shared.global [%0], [%1], 16;" :: "r"(dst), "l"(src) : "memory");
}
__device__ __forceinline__ void cp_commit() { asm volatile("cp.async.commit_group;" ::: "memory"); }
__device__ __forceinline__ void cp_wait0() { asm volatile("cp.async.wait_group 0;" ::: "memory"); }
__device__ __forceinline__ void lds64(uint32_t& a, uint32_t& b, uint32_t addr) {
    asm volatile("ld.shared.v2.u32 {%0,%1}, [%2];" : "=r"(a), "=r"(b) : "r"(addr));
}
__device__ __forceinline__ int ld_acquire(const int* p) {
    int v;
    asm volatile("ld.acquire.gpu.b32 %0, [%1];" : "=r"(v) : "l"(p) : "memory");
    return v;
}

// bf16 split (h1 path)
__device__ __forceinline__ uint32_t pack2(float f0, float f1) {
    uint32_t r;
    asm("cvt.rn.bf16x2.f32 %0, %1, %2;" : "=r"(r) : "f"(f1), "f"(f0));
    return r;
}
__device__ __forceinline__ void split2(float f0, float f1, uint32_t& h, uint32_t& l) {
    h = pack2(f0, f1);
    float h0 = __uint_as_float(h << 16);
    float h1 = __uint_as_float(h & 0xffff0000u);
    l = pack2(f0 - h0, f1 - h1);
}
__device__ __forceinline__ void split8(float4 v0, float4 v1, uint4& H, uint4& L) {
    split2(v0.x, v0.y, H.x, L.x);
    split2(v0.z, v0.w, H.y, L.y);
    split2(v1.x, v1.y, H.z, L.z);
    split2(v1.z, v1.w, H.w, L.w);
}
// fp16 pack / split (h2 path)
__device__ __forceinline__ uint32_t packh2(float f0, float f1) {
    uint32_t r;
    asm("cvt.rn.f16x2.f32 %0, %1, %2;" : "=r"(r) : "f"(f1), "f"(f0));
    return r;
}
__device__ __forceinline__ void split2h(float f0, float f1, uint32_t& h, uint32_t& l) {
    h = packh2(f0, f1);
    __half2 hh = *(__half2*)&h;
    l = packh2(f0 - __low2float(hh), f1 - __high2float(hh));
}

// ---------------- fused prep kernel ----------------
// [0,128) init_out | [128,256) fill_pad(fp16) | [256,2304) split_state(bf16)
// [2304,2624) split_W1(bf16) | [2624,2912) W2 frags(fp16) | [2912,3168) Btail frags(fp16) | [3168] zero
#define PREP_BLOCKS 3169
__global__ __launch_bounds__(256) void prep_kernel(const float* __restrict__ state,
                                                   const float* __restrict__ action,
                                                   const int* __restrict__ idx,
                                                   const float* __restrict__ W1,
                                                   const float* __restrict__ W2s,
                                                   const float* __restrict__ W2a,
                                                   const float* __restrict__ b3,
                                                   float* __restrict__ out) {
    const int blk = blockIdx.x;
    const int t = threadIdx.x;
    if (blk < 128) {
        int i = blk * 256 + t;
        out[i] = b3[idx[i]];
    } else if (blk < 256) {
        int b = (blk - 128) * 256 + t;
        const float4* a4 = (const float4*)(action + (size_t)b * A_DIM);
        float4 v0 = a4[0], v1 = a4[1], v2 = a4[2], v3 = a4[3];
        uint32_t* p = (uint32_t*)((uint16_t*)g_h1f + (size_t)b * KP + 600);
        p[0] = packh2(v0.x, v0.y); p[1] = packh2(v0.z, v0.w);
        p[2] = packh2(v1.x, v1.y); p[3] = packh2(v1.z, v1.w);
        p[4] = packh2(v2.x, v2.y); p[5] = packh2(v2.z, v2.w);
        p[6] = packh2(v3.x, v3.y); p[7] = packh2(v3.z, v3.w);
        #pragma unroll
        for (int j = 8; j < 20; j++) p[j] = 0u;   // cols 616..639 zero
    } else if (blk < 2304) {
        size_t e = ((size_t)(blk - 256) * 256 + t) * 8;
        const float4* s4 = (const float4*)(state + e);
        uint4 H, L;
        split8(s4[0], s4[1], H, L);
        *(uint4*)((uint16_t*)g_Sh + e) = H;
        *(uint4*)((uint16_t*)g_Sl + e) = L;
    } else if (blk < 2624) {
        size_t e = ((size_t)(blk - 2304) * 256 + t) * 8;
        int g = (int)(e / (640 * D_IN));
        int r = (int)((e / D_IN) % 640);
        int c = (int)(e % D_IN);
        uint4 H = make_uint4(0, 0, 0, 0), L = H;
        if (r < H1D) {
            const float4* s4 = (const float4*)(W1 + ((size_t)g * H1D + r) * D_IN + c);
            split8(s4[0], s4[1], H, L);
        }
        *(uint4*)((uint16_t*)g_W1h + e) = H;
        *(uint4*)((uint16_t*)g_W1l + e) = L;
    } else if (blk < 2912) {
        int u = (blk - 2624) * 256 + t;     // [0, 73728)
        int lane = u & 31;
        int n8 = (u >> 5) & 63;
        int kq = u >> 11;
        int n = n8 * 8 + (lane >> 2);
        int k0 = kq * 16 + (lane & 3) * 2;
        float x0 = 0.f, x1 = 0.f, x2 = 0.f, x3 = 0.f;
        if (n < H2D) {
            const float* w = W2s + (size_t)n * H1D;
            x0 = w[k0]; x1 = w[k0 + 1]; x2 = w[k0 + 8]; x3 = w[k0 + 9];
        }
        uint32_t h0, l0, h1, l1;
        split2h(x0, x1, h0, l0);
        split2h(x2, x3, h1, l1);
        size_t base = ((size_t)(kq * 64 + n8) * 2) * 32 + lane;
        g_W2f[base]      = (uint64_t)h0 | ((uint64_t)h1 << 32);
        g_W2f[base + 32] = (uint64_t)l0 | ((uint64_t)l1 << 32);
    } else if (blk < 3168) {
        int u = (blk - 2912) * 256 + t;     // [0, 65536)
        int lane = u & 31;
        int n8 = (u >> 5) & 63;
        int gk = u >> 11;
        int g = gk >> 2, kk = gk & 3;
        int n = n8 * 8 + (lane >> 2);
        int c0 = kk * 16 + (lane & 3) * 2;
        float v[4];
        const int off[4] = {0, 1, 8, 9};
        #pragma unroll
        for (int j = 0; j < 4; j++) {
            int tc = 576 + c0 + off[j];
            float x = 0.f;
            if (n < H2D) {
                if (tc < H1D) x = W2s[(size_t)n * H1D + tc];
                else if (tc < H1D + A_DIM) x = W2a[((size_t)g * H2D + n) * A_DIM + (tc - H1D)];
            }
            v[j] = x;
        }
        uint32_t h0, l0, h1, l1;
        split2h(v[0], v[1], h0, l0);
        split2h(v[2], v[3], h1, l1);
        size_t base = ((size_t)(gk * 64 + n8) * 2) * 32 + lane;
        g_Btf[base]      = (uint64_t)h0 | ((uint64_t)h1 << 32);
        g_Btf[base + 32] = (uint64_t)l0 | ((uint64_t)l1 << 32);
    } else {
        g_done[t] = 0;
    }
}

// ---------------- fused GEMM kernel ----------------
#define MMA_STAGE1(sbase, s)                                                       \
    {                                                                              \
        const uint32_t SA = (sbase) + (uint32_t)(s) * H1_STAGE;                    \
        const uint32_t SAh = SA, SAl = SA + H1_AHALF;                              \
        const uint32_t SBh = SA + 2u * H1_AHALF, SBl = SBh + H1_BHALF;             \
        _Pragma("unroll")                                                          \
        for (int kk = 0; kk < 4; kk++) {                                           \
            uint32_t ah[2][4], al[2][4], bh[4][2], bl[4][2];                       \
            _Pragma("unroll")                                                      \
            for (int mf = 0; mf < 2; mf++) {                                       \
                ldm_x4(ah[mf], SAh + aoff + mf * 2304u + kk * 32u);                \
                ldm_x4(al[mf], SAl + aoff + mf * 2304u + kk * 32u);                \
            }                                                                      \
            _Pragma("unroll")                                                      \
            for (int nq = 0; nq < 2; nq++) {                                       \
                uint32_t t[4];                                                     \
                ldm_x4(t, SBh + boff + nq * 2304u + kk * 32u);                     \
                bh[nq * 2][0] = t[0]; bh[nq * 2][1] = t[2];                        \
                bh[nq * 2 + 1][0] = t[1]; bh[nq * 2 + 1][1] = t[3];                \
                ldm_x4(t, SBl + boff + nq * 2304u + kk * 32u);                     \
                bl[nq * 2][0] = t[0]; bl[nq * 2][1] = t[2];                        \
                bl[nq * 2 + 1][0] = t[1]; bl[nq * 2 + 1][1] = t[3];                \
            }                                                                      \
            _Pragma("unroll")                                                      \
            for (int mf = 0; mf < 2; mf++)                                         \
                _Pragma("unroll")                                                  \
                for (int nf = 0; nf < 4; nf++) {                                   \
                    mma_bf16(C[mf][nf], ah[mf], bh[nf]);                           \
                    mma_bf16(C[mf][nf], ah[mf], bl[nf]);                           \
                    mma_bf16(C[mf][nf], al[mf], bh[nf]);                           \
                }                                                                  \
        }                                                                          \
    }

__global__ __launch_bounds__(256, 2) void fused_mma_kernel(const int* __restrict__ idx,
                                                           const float* __restrict__ b1,
                                                           const float* __restrict__ b2s,
                                                           const float* __restrict__ W3,
                                                           float* __restrict__ out) {
    extern __shared__ char dsm[];
    const uint32_t sbase = smem_u32(dsm);
    const int tid = threadIdx.x, lane = tid & 31, wid = tid >> 5;

    if (blockIdx.x < 2560) {
        // ================= h1 tile (bf16 3-term, R10-proven) =================
        const int b_blk = blockIdx.x / 10, n_idx = blockIdx.x % 10;
        const int n0 = n_idx * 64, b0 = b_blk * 128;
        float* sb1 = (float*)(dsm + 2 * H1_STAGE);
        int* sidx = (int*)(sb1 + 64);
        if (tid < 128) sidx[tid] = idx[b0 + tid];
        __syncthreads();
        const int g_lo = sidx[0], g_hi = sidx[127];
        const int m_base = (wid >> 1) * 32, n_base = (wid & 1) * 32;
        const uint32_t aoff = (uint32_t)(m_base + (lane & 15)) * H1_ROWB + (uint32_t)((lane >> 4) * 16);
        const uint32_t boff = (uint32_t)(n_base + (lane & 15)) * H1_ROWB + (uint32_t)((lane >> 4) * 16);

        for (int g = g_lo; g <= g_hi; ++g) {
            if (tid < 64) { int n = n0 + tid; sb1[tid] = (n < H1D) ? b1[(size_t)g * H1D + n] : 0.f; }
            auto issue = [&](int kc, int s) {
                #pragma unroll
                for (int i = 0; i < 8; i++) {
                    int bid = tid + i * 256;
                    int arr = bid >> 10, rem = bid & 1023;
                    int row = rem >> 3, q = rem & 7;
                    const __nv_bfloat16* src = (arr ? g_Sl : g_Sh) + (size_t)(b0 + row) * D_IN + kc * 64 + q * 8;
                    cp16(sbase + (uint32_t)s * H1_STAGE + (uint32_t)arr * H1_AHALF + row * H1_ROWB + q * 16u, src);
                }
                #pragma unroll
                for (int i = 0; i < 4; i++) {
                    int bid = tid + i * 256;
                    int arr = bid >> 9, rem = bid & 511;
                    int row = rem >> 3, q = rem & 7;
                    const __nv_bfloat16* src = (arr ? g_W1l : g_W1h) + ((size_t)g * 640 + n0 + row) * D_IN + kc * 64 + q * 8;
                    cp16(sbase + (uint32_t)s * H1_STAGE + 2u * H1_AHALF + (uint32_t)arr * H1_BHALF + row * H1_ROWB + q * 16u, src);
                }
                cp_commit();
            };
            float C[2][4][4];
            #pragma unroll
            for (int mf = 0; mf < 2; mf++)
                #pragma unroll
                for (int nf = 0; nf < 4; nf++)
                    #pragma unroll
                    for (int e = 0; e < 4; e++) C[mf][nf][e] = 0.f;

            issue(0, 0);
            cp_wait0();
            __syncthreads();
            issue(1, 1);
            MMA_STAGE1(sbase, 0);
            cp_wait0();
            __syncthreads();
            MMA_STAGE1(sbase, 1);

            #pragma unroll
            for (int mf = 0; mf < 2; mf++)
                #pragma unroll
                for (int half = 0; half < 2; half++) {
                    int r = m_base + mf * 16 + (lane >> 2) + half * 8;
                    if (sidx[r] == g) {
                        size_t base = (size_t)(b0 + r) * KP;
                        #pragma unroll
                        for (int nf = 0; nf < 4; nf++) {
                            int lc = n_base + nf * 8 + 2 * (lane & 3);
                            int n = n0 + lc;
                            if (n < H1D) {
                                float v0 = fmaxf(C[mf][nf][half * 2 + 0] + sb1[lc], 0.f);
                                float v1 = fmaxf(C[mf][nf][half * 2 + 1] + sb1[lc + 1], 0.f);
                                *(uint32_t*)((uint16_t*)g_h1f + base + n) = packh2(v0, v1);
                            }
                        }
                    }
                }
            __syncthreads();
        }
        __threadfence();
        __syncthreads();
        if (tid == 0) atomicAdd(&g_done[b_blk], 1);
    } else {
        // ================= h2q tile (fp16 2-term) =================
        const int tix = blockIdx.x - 2560;
        const int b_blk = tix / 8, n_idx = tix % 8;
        const int n0 = n_idx * 64, b0 = b_blk * 128;
        float* sb2 = (float*)(dsm + 2 * A2STG + 2 * BSTG);
        float* sw3 = sb2 + 64;
        int* sidx = (int*)(sw3 + 64);
        if (tid < 128) sidx[tid] = idx[b0 + tid];
        if (tid < 64) { int n = n0 + tid; sb2[tid] = (n < H2D) ? b2s[n] : 0.f; }
        if (tid == 0) {
            while (ld_acquire(&g_done[b_blk]) < 10) {}
        }
        __syncthreads();
        const int g_lo = sidx[0], g_hi = sidx[127];
        const int m_base = (wid >> 1) * 32;
        const int nhalf = wid & 1;
        const uint32_t aoff = (uint32_t)(m_base + (lane & 15)) * ROWB + (uint32_t)((lane >> 4) * 16);
        const int ng0 = n0 >> 3;

        for (int g = g_lo; g <= g_hi; ++g) {
            if (tid < 64) { int n = n0 + tid; sw3[tid] = (n < H2D) ? W3[(size_t)g * H2D + n] : 0.f; }

            auto issue = [&](int kc, int s) {
                // A: 1024 16B blocks (128 rows x 8 q) of fp16 h1
                #pragma unroll
                for (int i = 0; i < 4; i++) {
                    int bid = tid + i * 256;
                    int row = bid >> 3, q = bid & 7;
                    const __half* src = g_h1f + (size_t)(b0 + row) * KP + kc * 64 + q * 8;
                    cp16(sbase + (uint32_t)s * A2STG + row * ROWB + q * 16u, src);
                }
                const char* bsrc = (kc < 9) ? (const char*)g_W2f : (const char*)g_Btf;
                #pragma unroll
                for (int i = 0; i < 4; i++) {
                    int bid = tid + i * 256;
                    int kk = bid >> 8, w = bid & 255;
                    size_t goff = (kc < 9)
                        ? ((size_t)((kc * 4 + kk) * 64 + ng0) * 512 + (size_t)w * 16)
                        : ((size_t)((g  * 4 + kk) * 64 + ng0) * 512 + (size_t)w * 16);
                    cp16(sbase + H2_BOFF + (uint32_t)s * BSTG + (uint32_t)kk * 4096u + (uint32_t)w * 16u,
                         bsrc + goff);
                }
                cp_commit();
            };
            auto ldsB = [&](uint32_t (&bb)[4][2][2], uint32_t Bkk) {
                #pragma unroll
                for (int nf = 0; nf < 4; nf++)
                    #pragma unroll
                    for (int h = 0; h < 2; h++) {
                        uint32_t addr = Bkk + (uint32_t)(((nhalf * 4 + nf) * 2 + h) * 256) + (uint32_t)lane * 8u;
                        lds64(bb[nf][h][0], bb[nf][h][1], addr);
                    }
            };

            float C[2][4][4];
            #pragma unroll
            for (int mf = 0; mf < 2; mf++)
                #pragma unroll
                for (int nf = 0; nf < 4; nf++)
                    #pragma unroll
                    for (int e = 0; e < 4; e++) C[mf][nf][e] = 0.f;

            issue(0, 0);
            for (int kc = 0; kc < 10; ++kc) {
                cp_wait0();
                __syncthreads();
                if (kc < 9) issue(kc + 1, (kc + 1) & 1);
                const uint32_t SA = sbase + (uint32_t)(kc & 1) * A2STG;
                const uint32_t Bs = sbase + H2_BOFF + (uint32_t)(kc & 1) * BSTG;
                uint32_t bb[2][4][2][2];
                ldsB(bb[0], Bs);
                #pragma unroll
                for (int kk = 0; kk < 4; kk++) {
                    const int p = kk & 1;
                    if (kk < 3) ldsB(bb[p ^ 1], Bs + (uint32_t)(kk + 1) * 4096u);
                    uint32_t ah[2][4];
                    #pragma unroll
                    for (int mf = 0; mf < 2; mf++)
                        ldm_x4(ah[mf], SA + aoff + mf * 2304u + kk * 32u);
                    #pragma unroll
                    for (int mf = 0; mf < 2; mf++)
                        #pragma unroll
                        for (int nf = 0; nf < 4; nf++) {
                            mma_f16(C[mf][nf], ah[mf], bb[p][nf][0]);
                            mma_f16(C[mf][nf], ah[mf], bb[p][nf][1]);
                        }
                }
            }

            #pragma unroll
            for (int mf = 0; mf < 2; mf++)
                #pragma unroll
                for (int half = 0; half < 2; half++) {
                    int r = m_base + mf * 16 + (lane >> 2) + half * 8;
                    float qp = 0.f;
                    #pragma unroll
                    for (int nf = 0; nf < 4; nf++) {
                        int lc = nhalf * 32 + nf * 8 + 2 * (lane & 3);
                        qp += fmaxf(C[mf][nf][half * 2 + 0] + sb2[lc], 0.f) * sw3[lc];
                        qp += fmaxf(C[mf][nf][half * 2 + 1] + sb2[lc + 1], 0.f) * sw3[lc + 1];
                    }
                    qp += __shfl_xor_sync(0xffffffffu, qp, 1);
                    qp += __shfl_xor_sync(0xffffffffu, qp, 2);
                    if ((lane & 3) == 0 && sidx[r] == g) atomicAdd(out + b0 + r, qp);
                }
            __syncthreads();
        }
    }
}

extern "C" void kernel_launch(void* const* d_in, const int* in_sizes, int n_in,
                              void* d_out, int out_size) {
    const float* state  = (const float*)d_in[0];
    const float* action = (const float*)d_in[1];
    const int*   idx    = (const int*)d_in[2];
    const float* W1     = (const float*)d_in[3];
    const float* b1     = (const float*)d_in[4];
    const float* W2s    = (const float*)d_in[5];
    const float* b2s    = (const float*)d_in[6];
    const float* W2a    = (const float*)d_in[7];
    const float* W3     = (const float*)d_in[8];
    const float* b3     = (const float*)d_in[9];
    float* out = (float*)d_out;

    cudaFuncSetAttribute(fused_mma_kernel, cudaFuncAttributeMaxDynamicSharedMemorySize, FUSED_SMEM);

    prep_kernel<<<PREP_BLOCKS, 256>>>(state, action, idx, W1, W2s, W2a, b3, out);
    fused_mma_kernel<<<4608, 256, FUSED_SMEM>>>(idx, b1, b2s, W3, out);
}

// round 17
// speedup vs baseline: 1.8442x; 1.0819x over previous
#include <cuda_runtime.h>
#include <cuda_bf16.h>
#include <cuda_fp16.h>
#include <cstdint>
#include <cstddef>

#define B_TOT 32768
#define D_IN  128
#define A_DIM 16
#define H1D   600
#define H2D   500
#define KP    640
#define G_N   8

// ---- h1 geometry: fp16 single-A + fp16 hi/lo B, 2 stages ----
#define H1_ROWB   144u
#define H1_ASZ    18432u            // 128 rows x 144B (fp16 A, single)
#define H1_BHALF  9216u             // 64 rows x 144B per half
#define H1_STAGE  (H1_ASZ + 2u*H1_BHALF)   // 36864
#define H1_SMEM   (2*H1_STAGE + 1024)      // 74752

// ---- h2q geometry (R16-proven): fp16 A single 2-stage + B fragment 2-stage ----
#define ROWB    144u
#define A2STG   18432u
#define BSTG    16384u
#define H2_BOFF (2u*A2STG)          // 36864
#define H2_SMEM (2*A2STG + 2*BSTG + 1024)   // 70656

#define FUSED_SMEM (H1_SMEM > H2_SMEM ? H1_SMEM : H2_SMEM)

// ---- persistent device scratch ----
__device__ __half g_h1f[(size_t)B_TOT * KP];       // fp16 h1 activations (+action pad)
__device__ __half g_Sf[(size_t)B_TOT * D_IN];      // fp16 state (single)
__device__ __half g_W1h[(size_t)G_N * 640 * D_IN]; // fp16 W1 hi
__device__ __half g_W1l[(size_t)G_N * 640 * D_IN]; // fp16 W1 lo
// B fragments (fp16 hi/lo): unit = ((kstep*64 + n8)*2 + h)*32 + lane, 8B each
__device__ uint64_t g_W2f[(size_t)36 * 64 * 2 * 32];
__device__ uint64_t g_Btf[(size_t)G_N * 4 * 64 * 2 * 32];
__device__ int g_done[256];

// ---------------- helpers ----------------
__device__ __forceinline__ uint32_t smem_u32(const void* p) {
    uint32_t a;
    asm("{ .reg .u64 t; cvta.to.shared.u64 t, %1; cvt.u32.u64 %0, t; }" : "=r"(a) : "l"(p));
    return a;
}
__device__ __forceinline__ void ldm_x4(uint32_t* r, uint32_t addr) {
    asm volatile("ldmatrix.sync.aligned.m8n8.x4.shared.b16 {%0,%1,%2,%3}, [%4];"
                 : "=r"(r[0]), "=r"(r[1]), "=r"(r[2]), "=r"(r[3]) : "r"(addr));
}
__device__ __forceinline__ void mma_f16(float* c, const uint32_t* a, const uint32_t* b) {
    asm volatile("mma.sync.aligned.m16n8k16.row.col.f32.f16.f16.f32 "
                 "{%0,%1,%2,%3}, {%4,%5,%6,%7}, {%8,%9}, {%0,%1,%2,%3};"
                 : "+f"(c[0]), "+f"(c[1]), "+f"(c[2]), "+f"(c[3])
                 : "r"(a[0]), "r"(a[1]), "r"(a[2]), "r"(a[3]), "r"(b[0]), "r"(b[1]));
}
__device__ __forceinline__ void cp16(uint32_t dst, const void* src) {
    asm volatile("cp.async.cg.shared.global [%0], [%1], 16;" :: "r"(dst), "l"(src) : "memory");
}
__device__ __forceinline__ void cp_commit() { asm volatile("cp.async.commit_group;" ::: "memory"); }
__device__ __forceinline__ void cp_wait0() { asm volatile("cp.async.wait_group 0;" ::: "memory"); }
__device__ __forceinline__ void lds64(uint32_t& a, uint32_t& b, uint32_t addr) {
    asm volatile("ld.shared.v2.u32 {%0,%1}, [%2];" : "=r"(a), "=r"(b) : "r"(addr));
}
__device__ __forceinline__ int ld_acquire(const int* p) {
    int v;
    asm volatile("ld.acquire.gpu.b32 %0, [%1];" : "=r"(v) : "l"(p) : "memory");
    return v;
}

// fp16 pack / split
__device__ __forceinline__ uint32_t packh2(float f0, float f1) {
    uint32_t r;
    asm("cvt.rn.f16x2.f32 %0, %1, %2;" : "=r"(r) : "f"(f1), "f"(f0));
    return r;
}
__device__ __forceinline__ void split2h(float f0, float f1, uint32_t& h, uint32_t& l) {
    h = packh2(f0, f1);
    __half2 hh = *(__half2*)&h;
    l = packh2(f0 - __low2float(hh), f1 - __high2float(hh));
}
__device__ __forceinline__ void split8h(float4 v0, float4 v1, uint4& H, uint4& L) {
    split2h(v0.x, v0.y, H.x, L.x);
    split2h(v0.z, v0.w, H.y, L.y);
    split2h(v1.x, v1.y, H.z, L.z);
    split2h(v1.z, v1.w, H.w, L.w);
}
__device__ __forceinline__ uint4 pack8h(float4 v0, float4 v1) {
    uint4 r;
    r.x = packh2(v0.x, v0.y); r.y = packh2(v0.z, v0.w);
    r.z = packh2(v1.x, v1.y); r.w = packh2(v1.z, v1.w);
    return r;
}

// ---------------- fused prep kernel ----------------
// [0,128) init_out | [128,256) fill_pad(fp16) | [256,2304) state->fp16
// [2304,2624) W1 split fp16 | [2624,2912) W2 frags | [2912,3168) Btail frags | [3168] zero
#define PREP_BLOCKS 3169
__global__ __launch_bounds__(256) void prep_kernel(const float* __restrict__ state,
                                                   const float* __restrict__ action,
                                                   const int* __restrict__ idx,
                                                   const float* __restrict__ W1,
                                                   const float* __restrict__ W2s,
                                                   const float* __restrict__ W2a,
                                                   const float* __restrict__ b3,
                                                   float* __restrict__ out) {
    const int blk = blockIdx.x;
    const int t = threadIdx.x;
    if (blk < 128) {
        int i = blk * 256 + t;
        out[i] = b3[idx[i]];
    } else if (blk < 256) {
        int b = (blk - 128) * 256 + t;
        const float4* a4 = (const float4*)(action + (size_t)b * A_DIM);
        float4 v0 = a4[0], v1 = a4[1], v2 = a4[2], v3 = a4[3];
        uint32_t* p = (uint32_t*)((uint16_t*)g_h1f + (size_t)b * KP + 600);
        p[0] = packh2(v0.x, v0.y); p[1] = packh2(v0.z, v0.w);
        p[2] = packh2(v1.x, v1.y); p[3] = packh2(v1.z, v1.w);
        p[4] = packh2(v2.x, v2.y); p[5] = packh2(v2.z, v2.w);
        p[6] = packh2(v3.x, v3.y); p[7] = packh2(v3.z, v3.w);
        #pragma unroll
        for (int j = 8; j < 20; j++) p[j] = 0u;
    } else if (blk < 2304) {
        size_t e = ((size_t)(blk - 256) * 256 + t) * 8;
        const float4* s4 = (const float4*)(state + e);
        *(uint4*)((uint16_t*)g_Sf + e) = pack8h(s4[0], s4[1]);
    } else if (blk < 2624) {
        size_t e = ((size_t)(blk - 2304) * 256 + t) * 8;
        int g = (int)(e / (640 * D_IN));
        int r = (int)((e / D_IN) % 640);
        int c = (int)(e % D_IN);
        uint4 H = make_uint4(0, 0, 0, 0), L = H;
        if (r < H1D) {
            const float4* s4 = (const float4*)(W1 + ((size_t)g * H1D + r) * D_IN + c);
            split8h(s4[0], s4[1], H, L);
        }
        *(uint4*)((uint16_t*)g_W1h + e) = H;
        *(uint4*)((uint16_t*)g_W1l + e) = L;
    } else if (blk < 2912) {
        int u = (blk - 2624) * 256 + t;     // [0, 73728)
        int lane = u & 31;
        int n8 = (u >> 5) & 63;
        int kq = u >> 11;
        int n = n8 * 8 + (lane >> 2);
        int k0 = kq * 16 + (lane & 3) * 2;
        float x0 = 0.f, x1 = 0.f, x2 = 0.f, x3 = 0.f;
        if (n < H2D) {
            const float* w = W2s + (size_t)n * H1D;
            x0 = w[k0]; x1 = w[k0 + 1]; x2 = w[k0 + 8]; x3 = w[k0 + 9];
        }
        uint32_t h0, l0, h1, l1;
        split2h(x0, x1, h0, l0);
        split2h(x2, x3, h1, l1);
        size_t base = ((size_t)(kq * 64 + n8) * 2) * 32 + lane;
        g_W2f[base]      = (uint64_t)h0 | ((uint64_t)h1 << 32);
        g_W2f[base + 32] = (uint64_t)l0 | ((uint64_t)l1 << 32);
    } else if (blk < 3168) {
        int u = (blk - 2912) * 256 + t;     // [0, 65536)
        int lane = u & 31;
        int n8 = (u >> 5) & 63;
        int gk = u >> 11;
        int g = gk >> 2, kk = gk & 3;
        int n = n8 * 8 + (lane >> 2);
        int c0 = kk * 16 + (lane & 3) * 2;
        float v[4];
        const int off[4] = {0, 1, 8, 9};
        #pragma unroll
        for (int j = 0; j < 4; j++) {
            int tc = 576 + c0 + off[j];
            float x = 0.f;
            if (n < H2D) {
                if (tc < H1D) x = W2s[(size_t)n * H1D + tc];
                else if (tc < H1D + A_DIM) x = W2a[((size_t)g * H2D + n) * A_DIM + (tc - H1D)];
            }
            v[j] = x;
        }
        uint32_t h0, l0, h1, l1;
        split2h(v[0], v[1], h0, l0);
        split2h(v[2], v[3], h1, l1);
        size_t base = ((size_t)(gk * 64 + n8) * 2) * 32 + lane;
        g_Btf[base]      = (uint64_t)h0 | ((uint64_t)h1 << 32);
        g_Btf[base + 32] = (uint64_t)l0 | ((uint64_t)l1 << 32);
    } else {
        g_done[t] = 0;
    }
}

// ---------------- fused GEMM kernel ----------------
// h1 MMA body: fp16 single A, fp16 hi/lo B, 16 MMAs per kk
#define MMA_STAGE1(sbase, s)                                                       \
    {                                                                              \
        const uint32_t SA = (sbase) + (uint32_t)(s) * H1_STAGE;                    \
        const uint32_t SBh = SA + H1_ASZ, SBl = SBh + H1_BHALF;                    \
        _Pragma("unroll")                                                          \
        for (int kk = 0; kk < 4; kk++) {                                           \
            uint32_t ah[2][4], bh[4][2], bl[4][2];                                 \
            _Pragma("unroll")                                                      \
            for (int mf = 0; mf < 2; mf++)                                         \
                ldm_x4(ah[mf], SA + aoff + mf * 2304u + kk * 32u);                 \
            _Pragma("unroll")                                                      \
            for (int nq = 0; nq < 2; nq++) {                                       \
                uint32_t t[4];                                                     \
                ldm_x4(t, SBh + boff + nq * 2304u + kk * 32u);                     \
                bh[nq * 2][0] = t[0]; bh[nq * 2][1] = t[2];                        \
                bh[nq * 2 + 1][0] = t[1]; bh[nq * 2 + 1][1] = t[3];                \
                ldm_x4(t, SBl + boff + nq * 2304u + kk * 32u);                     \
                bl[nq * 2][0] = t[0]; bl[nq * 2][1] = t[2];                        \
                bl[nq * 2 + 1][0] = t[1]; bl[nq * 2 + 1][1] = t[3];                \
            }                                                                      \
            _Pragma("unroll")                                                      \
            for (int mf = 0; mf < 2; mf++)                                         \
                _Pragma("unroll")                                                  \
                for (int nf = 0; nf < 4; nf++) {                                   \
                    mma_f16(C[mf][nf], ah[mf], bh[nf]);                            \
                    mma_f16(C[mf][nf], ah[mf], bl[nf]);                            \
                }                                                                  \
        }                                                                          \
    }

__global__ __launch_bounds__(256, 2) void fused_mma_kernel(const int* __restrict__ idx,
                                                           const float* __restrict__ b1,
                                                           const float* __restrict__ b2s,
                                                           const float* __restrict__ W3,
                                                           float* __restrict__ out) {
    extern __shared__ char dsm[];
    const uint32_t sbase = smem_u32(dsm);
    const int tid = threadIdx.x, lane = tid & 31, wid = tid >> 5;

    if (blockIdx.x < 2560) {
        // ================= h1 tile (fp16 2-term) =================
        const int b_blk = blockIdx.x / 10, n_idx = blockIdx.x % 10;
        const int n0 = n_idx * 64, b0 = b_blk * 128;
        float* sb1 = (float*)(dsm + 2 * H1_STAGE);
        int* sidx = (int*)(sb1 + 64);
        if (tid < 128) sidx[tid] = idx[b0 + tid];
        __syncthreads();
        const int g_lo = sidx[0], g_hi = sidx[127];
        const int m_base = (wid >> 1) * 32, n_base = (wid & 1) * 32;
        const uint32_t aoff = (uint32_t)(m_base + (lane & 15)) * H1_ROWB + (uint32_t)((lane >> 4) * 16);
        const uint32_t boff = (uint32_t)(n_base + (lane & 15)) * H1_ROWB + (uint32_t)((lane >> 4) * 16);

        for (int g = g_lo; g <= g_hi; ++g) {
            if (tid < 64) { int n = n0 + tid; sb1[tid] = (n < H1D) ? b1[(size_t)g * H1D + n] : 0.f; }
            auto issue = [&](int kc, int s) {
                // A: 1024 16B blocks (128 rows x 8 q) fp16 state
                #pragma unroll
                for (int i = 0; i < 4; i++) {
                    int bid = tid + i * 256;
                    int row = bid >> 3, q = bid & 7;
                    const __half* src = g_Sf + (size_t)(b0 + row) * D_IN + kc * 64 + q * 8;
                    cp16(sbase + (uint32_t)s * H1_STAGE + row * H1_ROWB + q * 16u, src);
                }
                // B: 1024 16B blocks (2 halves x 64 rows x 8 q) fp16 W1
                #pragma unroll
                for (int i = 0; i < 4; i++) {
                    int bid = tid + i * 256;
                    int arr = bid >> 9, rem = bid & 511;
                    int row = rem >> 3, q = rem & 7;
                    const __half* src = (arr ? g_W1l : g_W1h) + ((size_t)g * 640 + n0 + row) * D_IN + kc * 64 + q * 8;
                    cp16(sbase + (uint32_t)s * H1_STAGE + H1_ASZ + (uint32_t)arr * H1_BHALF + row * H1_ROWB + q * 16u, src);
                }
                cp_commit();
            };
            float C[2][4][4];
            #pragma unroll
            for (int mf = 0; mf < 2; mf++)
                #pragma unroll
                for (int nf = 0; nf < 4; nf++)
                    #pragma unroll
                    for (int e = 0; e < 4; e++) C[mf][nf][e] = 0.f;

            issue(0, 0);
            cp_wait0();
            __syncthreads();
            issue(1, 1);
            MMA_STAGE1(sbase, 0);
            cp_wait0();
            __syncthreads();
            MMA_STAGE1(sbase, 1);

            #pragma unroll
            for (int mf = 0; mf < 2; mf++)
                #pragma unroll
                for (int half = 0; half < 2; half++) {
                    int r = m_base + mf * 16 + (lane >> 2) + half * 8;
                    if (sidx[r] == g) {
                        size_t base = (size_t)(b0 + r) * KP;
                        #pragma unroll
                        for (int nf = 0; nf < 4; nf++) {
                            int lc = n_base + nf * 8 + 2 * (lane & 3);
                            int n = n0 + lc;
                            if (n < H1D) {
                                float v0 = fmaxf(C[mf][nf][half * 2 + 0] + sb1[lc], 0.f);
                                float v1 = fmaxf(C[mf][nf][half * 2 + 1] + sb1[lc + 1], 0.f);
                                *(uint32_t*)((uint16_t*)g_h1f + base + n) = packh2(v0, v1);
                            }
                        }
                    }
                }
            __syncthreads();
        }
        __threadfence();
        __syncthreads();
        if (tid == 0) atomicAdd(&g_done[b_blk], 1);
    } else {
        // ================= h2q tile (R16-proven fp16 2-term) =================
        const int tix = blockIdx.x - 2560;
        const int b_blk = tix / 8, n_idx = tix % 8;
        const int n0 = n_idx * 64, b0 = b_blk * 128;
        float* sb2 = (float*)(dsm + 2 * A2STG + 2 * BSTG);
        float* sw3 = sb2 + 64;
        int* sidx = (int*)(sw3 + 64);
        if (tid < 128) sidx[tid] = idx[b0 + tid];
        if (tid < 64) { int n = n0 + tid; sb2[tid] = (n < H2D) ? b2s[n] : 0.f; }
        if (tid == 0) {
            while (ld_acquire(&g_done[b_blk]) < 10) {}
        }
        __syncthreads();
        const int g_lo = sidx[0], g_hi = sidx[127];
        const int m_base = (wid >> 1) * 32;
        const int nhalf = wid & 1;
        const uint32_t aoff = (uint32_t)(m_base + (lane & 15)) * ROWB + (uint32_t)((lane >> 4) * 16);
        const int ng0 = n0 >> 3;

        for (int g = g_lo; g <= g_hi; ++g) {
            if (tid < 64) { int n = n0 + tid; sw3[tid] = (n < H2D) ? W3[(size_t)g * H2D + n] : 0.f; }

            auto issue = [&](int kc, int s) {
                #pragma unroll
                for (int i = 0; i < 4; i++) {
                    int bid = tid + i * 256;
                    int row = bid >> 3, q = bid & 7;
                    const __half* src = g_h1f + (size_t)(b0 + row) * KP + kc * 64 + q * 8;
                    cp16(sbase + (uint32_t)s * A2STG + row * ROWB + q * 16u, src);
                }
                const char* bsrc = (kc < 9) ? (const char*)g_W2f : (const char*)g_Btf;
                #pragma unroll
                for (int i = 0; i < 4; i++) {
                    int bid = tid + i * 256;
                    int kk = bid >> 8, w = bid & 255;
                    size_t goff = (kc < 9)
                        ? ((size_t)((kc * 4 + kk) * 64 + ng0) * 512 + (size_t)w * 16)
                        : ((size_t)((g  * 4 + kk) * 64 + ng0) * 512 + (size_t)w * 16);
                    cp16(sbase + H2_BOFF + (uint32_t)s * BSTG + (uint32_t)kk * 4096u + (uint32_t)w * 16u,
                         bsrc + goff);
                }
                cp_commit();
            };
            auto ldsB = [&](uint32_t (&bb)[4][2][2], uint32_t Bkk) {
                #pragma unroll
                for (int nf = 0; nf < 4; nf++)
                    #pragma unroll
                    for (int h = 0; h < 2; h++) {
                        uint32_t addr = Bkk + (uint32_t)(((nhalf * 4 + nf) * 2 + h) * 256) + (uint32_t)lane * 8u;
                        lds64(bb[nf][h][0], bb[nf][h][1], addr);
                    }
            };

            float C[2][4][4];
            #pragma unroll
            for (int mf = 0; mf < 2; mf++)
                #pragma unroll
                for (int nf = 0; nf < 4; nf++)
                    #pragma unroll
                    for (int e = 0; e < 4; e++) C[mf][nf][e] = 0.f;

            issue(0, 0);
            for (int kc = 0; kc < 10; ++kc) {
                cp_wait0();
                __syncthreads();
                if (kc < 9) issue(kc + 1, (kc + 1) & 1);
                const uint32_t SA = sbase + (uint32_t)(kc & 1) * A2STG;
                const uint32_t Bs = sbase + H2_BOFF + (uint32_t)(kc & 1) * BSTG;
                uint32_t bb[2][4][2][2];
                ldsB(bb[0], Bs);
                #pragma unroll
                for (int kk = 0; kk < 4; kk++) {
                    const int p = kk & 1;
                    if (kk < 3) ldsB(bb[p ^ 1], Bs + (uint32_t)(kk + 1) * 4096u);
                    uint32_t ah[2][4];
                    #pragma unroll
                    for (int mf = 0; mf < 2; mf++)
                        ldm_x4(ah[mf], SA + aoff + mf * 2304u + kk * 32u);
                    #pragma unroll
                    for (int mf = 0; mf < 2; mf++)
                        #pragma unroll
                        for (int nf = 0; nf < 4; nf++) {
                            mma_f16(C[mf][nf], ah[mf], bb[p][nf][0]);
                            mma_f16(C[mf][nf], ah[mf], bb[p][nf][1]);
                        }
                }
            }

            #pragma unroll
            for (int mf = 0; mf < 2; mf++)
                #pragma unroll
                for (int half = 0; half < 2; half++) {
                    int r = m_base + mf * 16 + (lane >> 2) + half * 8;
                    float qp = 0.f;
                    #pragma unroll
                    for (int nf = 0; nf < 4; nf++) {
                        int lc = nhalf * 32 + nf * 8 + 2 * (lane & 3);
                        qp += fmaxf(C[mf][nf][half * 2 + 0] + sb2[lc], 0.f) * sw3[lc];
                        qp += fmaxf(C[mf][nf][half * 2 + 1] + sb2[lc + 1], 0.f) * sw3[lc + 1];
                    }
                    qp += __shfl_xor_sync(0xffffffffu, qp, 1);
                    qp += __shfl_xor_sync(0xffffffffu, qp, 2);
                    if ((lane & 3) == 0 && sidx[r] == g) atomicAdd(out + b0 + r, qp);
                }
            __syncthreads();
        }
    }
}

extern "C" void kernel_launch(void* const* d_in, const int* in_sizes, int n_in,
                              void* d_out, int out_size) {
    const float* state  = (const float*)d_in[0];
    const float* action = (const float*)d_in[1];
    const int*   idx    = (const int*)d_in[2];
    const float* W1     = (const float*)d_in[3];
    const float* b1     = (const float*)d_in[4];
    const float* W2s    = (const float*)d_in[5];
    const float* b2s    = (const float*)d_in[6];
    const float* W2a    = (const float*)d_in[7];
    const float* W3     = (const float*)d_in[8];
    const float* b3     = (const float*)d_in[9];
    float* out = (float*)d_out;

    cudaFuncSetAttribute(fused_mma_kernel, cudaFuncAttributeMaxDynamicSharedMemorySize, FUSED_SMEM);

    prep_kernel<<<PREP_BLOCKS, 256>>>(state, action, idx, W1, W2s, W2a, b3, out);
    fused_mma_kernel<<<4608, 256, FUSED_SMEM>>>(idx, b1, b2s, W3, out);
}